// round 3
// baseline (speedup 1.0000x reference)
#include <cuda_runtime.h>
#include <math.h>

#define BATCH  4
#define SEQ    2048
#define DIM    512
#define HEADS  8
#define DHEAD  64
#define INNER  512
#define TRIPLE 1536
#define ROWS   (BATCH * SEQ)

typedef unsigned long long u64;

// ---------------- scratch (device globals) ----------------
__device__ float g_xn[ROWS * DIM];                    // layernormed x
__device__ float g_q [BATCH * HEADS * DHEAD * SEQ];   // [b,h,dh,n]  (d-major!)
__device__ float g_k [BATCH * HEADS * DHEAD * SEQ];   // [b,h,dh,n]  (d-major!)
__device__ float g_v [BATCH * HEADS * SEQ * DHEAD];   // [b,h,n,dh]
__device__ float g_ao[ROWS * INNER];                  // attention out [b,n,h*dh]

// ---------------- f32x2 helpers ----------------
__device__ __forceinline__ u64 f2_dup(float x) {
    u64 r; unsigned int u = __float_as_uint(x);
    asm("mov.b64 %0, {%1, %2};" : "=l"(r) : "r"(u), "r"(u));
    return r;
}
__device__ __forceinline__ void f2_fma(u64& d, u64 a, u64 b) {
    asm("fma.rn.f32x2 %0, %1, %2, %0;" : "+l"(d) : "l"(a), "l"(b));
}
__device__ __forceinline__ void f2_mul(u64& d, u64 a) {
    asm("mul.rn.f32x2 %0, %0, %1;" : "+l"(d) : "l"(a));
}
__device__ __forceinline__ float2 f2_unpack(u64 v) {
    unsigned int lo, hi;
    asm("mov.b64 {%0, %1}, %2;" : "=r"(lo), "=r"(hi) : "l"(v));
    return make_float2(__uint_as_float(lo), __uint_as_float(hi));
}

// ---------------------------------------------------------------- LayerNorm
__global__ __launch_bounds__(128)
void ln_kernel(const float* __restrict__ x,
               const float* __restrict__ gamma,
               const float* __restrict__ beta) {
    const int row = blockIdx.x;
    const int t   = threadIdx.x;
    float4 v = ((const float4*)(x + (size_t)row * DIM))[t];
    float s  = v.x + v.y + v.z + v.w;
    float ss = v.x*v.x + v.y*v.y + v.z*v.z + v.w*v.w;
    #pragma unroll
    for (int o = 16; o > 0; o >>= 1) {
        s  += __shfl_xor_sync(0xffffffffu, s,  o);
        ss += __shfl_xor_sync(0xffffffffu, ss, o);
    }
    __shared__ float sh_s[4], sh_ss[4];
    const int w = t >> 5;
    if ((t & 31) == 0) { sh_s[w] = s; sh_ss[w] = ss; }
    __syncthreads();
    s  = sh_s[0] + sh_s[1] + sh_s[2] + sh_s[3];
    ss = sh_ss[0] + sh_ss[1] + sh_ss[2] + sh_ss[3];
    const float mu  = s * (1.0f / DIM);
    const float var = ss * (1.0f / DIM) - mu * mu;
    const float inv = rsqrtf(var + 1e-5f);
    float4 g  = ((const float4*)gamma)[t];
    float4 be = ((const float4*)beta)[t];
    float4 o;
    o.x = (v.x - mu) * inv * g.x + be.x;
    o.y = (v.y - mu) * inv * g.y + be.y;
    o.z = (v.z - mu) * inv * g.z + be.z;
    o.w = (v.w - mu) * inv * g.w + be.w;
    ((float4*)(g_xn + (size_t)row * DIM))[t] = o;
}

// -------------------------------------------- f32x2 SGEMM 128x128, K-paired
// acc2[i][j] holds (sum over even k, sum over odd k); final = lo+hi.
// Register tile strided: rows ty + 16*i, cols tx + 16*j.
template<int NOUT, bool QKV_SCATTER>
__global__ __launch_bounds__(256, 1)
void sgemm2_kernel(const float* __restrict__ W, float* __restrict__ C) {
    constexpr int K = 512;
    __shared__ __align__(16) float2 As2[4][128];   // [kpair][m] = (A[m][2kk],A[m][2kk+1])
    __shared__ __align__(16) float2 Bs2[4][128];   // [kpair][n] = (B[2kk][n],B[2kk+1][n])

    const float* A = QKV_SCATTER ? g_xn : g_ao;

    const int tid = threadIdx.x;
    const int bm  = blockIdx.y * 128;
    const int bn  = blockIdx.x * 128;
    const int ty  = tid >> 4;
    const int tx  = tid & 15;
    const int lm  = tid >> 1;               // A row in tile
    const int lk4 = (tid & 1) << 2;         // 0 or 4
    const int br  = tid >> 6;               // 0..3 : k-pair row
    const int bn2 = (tid & 63) << 1;        // 0..126 : col pair base

    u64 acc2[8][8];
    #pragma unroll
    for (int i = 0; i < 8; ++i)
        #pragma unroll
        for (int j = 0; j < 8; ++j) acc2[i][j] = 0ull;

    const float* Aptr = A + (size_t)(bm + lm) * K + lk4;
    const float* Wptr = W + (size_t)(2 * br) * NOUT + bn + bn2;

    float4 pA  = *(const float4*)(Aptr);
    float2 pB0 = *(const float2*)(Wptr);
    float2 pB1 = *(const float2*)(Wptr + NOUT);

    for (int k0 = 0; k0 < K; k0 += 8) {
        const int kk0 = lk4 >> 1;           // 0 or 2
        As2[kk0    ][lm] = make_float2(pA.x, pA.y);
        As2[kk0 + 1][lm] = make_float2(pA.z, pA.w);
        Bs2[br][bn2    ] = make_float2(pB0.x, pB1.x);
        Bs2[br][bn2 + 1] = make_float2(pB0.y, pB1.y);
        __syncthreads();

        if (k0 + 8 < K) {
            pA  = *(const float4*)(Aptr + k0 + 8);
            pB0 = *(const float2*)(Wptr + (size_t)(k0 + 8) * NOUT);
            pB1 = *(const float2*)(Wptr + (size_t)(k0 + 9) * NOUT);
        }

        #pragma unroll
        for (int kk = 0; kk < 4; ++kk) {
            u64 a2[8], b2[8];
            #pragma unroll
            for (int i = 0; i < 8; ++i)
                a2[i] = *reinterpret_cast<const u64*>(&As2[kk][ty + 16 * i]);
            #pragma unroll
            for (int j = 0; j < 8; ++j)
                b2[j] = *reinterpret_cast<const u64*>(&Bs2[kk][tx + 16 * j]);
            #pragma unroll
            for (int i = 0; i < 8; ++i)
                #pragma unroll
                for (int j = 0; j < 8; ++j)
                    f2_fma(acc2[i][j], a2[i], b2[j]);
        }
        __syncthreads();
    }

    if (QKV_SCATTER) {
        #pragma unroll
        for (int i = 0; i < 8; ++i) {
            const int row = bm + ty + 16 * i;
            const int bb  = row >> 11;
            const int nn  = row & 2047;
            #pragma unroll
            for (int j = 0; j < 8; ++j) {
                const int col  = bn + tx + 16 * j;
                const int part = col >> 9;
                const int rem  = col & 511;
                const int h    = rem >> 6;
                const int d    = rem & 63;
                float2 p = f2_unpack(acc2[i][j]);
                const float val = p.x + p.y;
                if (part == 2) {
                    g_v[(((size_t)(bb * HEADS + h)) * SEQ + nn) * DHEAD + d] = val;
                } else {
                    float* dst = (part == 0) ? g_q : g_k;
                    dst[(((size_t)(bb * HEADS + h)) * DHEAD + d) * SEQ + nn] = val;
                }
            }
        }
    } else {
        #pragma unroll
        for (int i = 0; i < 8; ++i) {
            const int row = bm + ty + 16 * i;
            #pragma unroll
            for (int j = 0; j < 8; ++j) {
                float2 p = f2_unpack(acc2[i][j]);
                C[(size_t)row * NOUT + bn + tx + 16 * j] = p.x + p.y;
            }
        }
    }
}

// ------------------------------------------------- flash attention, f32x2
// Block: 128 threads, 64 queries x 64 keys per tile.
// Thread microtile: 4 q-rows (ty+16i) x 8 k-cols as 4 adjacent pairs
// (cols 2*(tx+8*j2) +{0,1}).  Q/K in d-major global layout -> plain copies.
__global__ __launch_bounds__(128)
void attn2_kernel(const float* __restrict__ pose_bias,
                  const float* __restrict__ beta_ptr) {
    __shared__ __align__(16) float Qs [64 * 64];   // [d][q]
    __shared__ __align__(16) float KPs[64 * 64];   // K: [d][j]; later P: [k][q]
    __shared__ __align__(16) float Vs [64 * 64];   // [j][d]

    const int tid = threadIdx.x;
    const int ty  = tid >> 3;      // 0..15
    const int tx  = tid & 7;       // 0..7
    const int q0  = blockIdx.x * 64;
    const int bh  = blockIdx.y;
    const int b   = bh >> 3;
    const int h   = bh & 7;

    const float bet   = *beta_ptr;
    const float scale = 0.125f;

    // load Q tile (d-major rows, straight copy)
    const float* qg = g_q + (size_t)bh * DHEAD * SEQ + q0;
    #pragma unroll
    for (int r = 0; r < 8; ++r) {
        int idx = tid + r * 128;
        int d   = idx >> 4;
        int c4  = (idx & 15) << 2;
        *(float4*)(&Qs[d * 64 + c4]) = *(const float4*)(qg + (size_t)d * SEQ + c4);
    }

    float bq[4];
    #pragma unroll
    for (int i = 0; i < 4; ++i)
        bq[i] = bet * __ldg(&pose_bias[(size_t)b * SEQ + q0 + ty + 16 * i]);

    float m_run[4], l_run[4];
    u64 o2[4][4];
    #pragma unroll
    for (int i = 0; i < 4; ++i) {
        m_run[i] = -INFINITY; l_run[i] = 0.f;
        #pragma unroll
        for (int j = 0; j < 4; ++j) o2[i][j] = 0ull;
    }

    const float* kg = g_k + (size_t)bh * DHEAD * SEQ;
    const float* vg = g_v + (size_t)bh * SEQ * DHEAD;

    for (int j0 = 0; j0 < SEQ; j0 += 64) {
        __syncthreads();   // prev PV done (and Q store visible on first iter)
        #pragma unroll
        for (int r = 0; r < 8; ++r) {
            int idx = tid + r * 128;
            int a   = idx >> 4;
            int c4  = (idx & 15) << 2;
            *(float4*)(&KPs[a * 64 + c4]) =
                *(const float4*)(kg + (size_t)a * SEQ + j0 + c4);
            *(float4*)(&Vs[a * 64 + c4]) =
                *(const float4*)(vg + (size_t)(j0 + a) * DHEAD + c4);
        }
        __syncthreads();

        // S = Q K^T : pairs over key columns
        u64 s2[4][4];
        #pragma unroll
        for (int i = 0; i < 4; ++i)
            #pragma unroll
            for (int j = 0; j < 4; ++j) s2[i][j] = 0ull;

        #pragma unroll 4
        for (int d = 0; d < 64; ++d) {
            u64 qp[4], kb[4];
            #pragma unroll
            for (int i = 0; i < 4; ++i)
                qp[i] = f2_dup(Qs[d * 64 + ty + 16 * i]);
            #pragma unroll
            for (int j = 0; j < 4; ++j)
                kb[j] = *reinterpret_cast<const u64*>(&KPs[d * 64 + 2 * (tx + 8 * j)]);
            #pragma unroll
            for (int i = 0; i < 4; ++i)
                #pragma unroll
                for (int j = 0; j < 4; ++j)
                    f2_fma(s2[i][j], qp[i], kb[j]);
        }
        __syncthreads();   // done reading K before P overwrites

        // key-column pose bias
        float2 bk[4];
        #pragma unroll
        for (int j = 0; j < 4; ++j) {
            float2 pb = *(const float2*)(&pose_bias[(size_t)b * SEQ + j0 + 2 * (tx + 8 * j)]);
            bk[j] = make_float2(bet * pb.x, bet * pb.y);
        }

        // online softmax (rows reduced over tx: shfl 1,2,4)
        #pragma unroll
        for (int i = 0; i < 4; ++i) {
            float sv[8];
            #pragma unroll
            for (int j = 0; j < 4; ++j) {
                float2 p = f2_unpack(s2[i][j]);
                sv[2 * j]     = p.x * scale + bq[i] + bk[j].x;
                sv[2 * j + 1] = p.y * scale + bq[i] + bk[j].y;
            }
            float tmax = sv[0];
            #pragma unroll
            for (int c = 1; c < 8; ++c) tmax = fmaxf(tmax, sv[c]);
            #pragma unroll
            for (int off = 1; off <= 4; off <<= 1)
                tmax = fmaxf(tmax, __shfl_xor_sync(0xffffffffu, tmax, off));
            const float m_new = fmaxf(m_run[i], tmax);
            const float corr  = __expf(m_run[i] - m_new);
            m_run[i] = m_new;
            float tsum = 0.f;
            #pragma unroll
            for (int c = 0; c < 8; ++c) {
                sv[c] = __expf(sv[c] - m_new);
                tsum += sv[c];
            }
            #pragma unroll
            for (int off = 1; off <= 4; off <<= 1)
                tsum += __shfl_xor_sync(0xffffffffu, tsum, off);
            l_run[i] = l_run[i] * corr + tsum;
            const u64 cd = f2_dup(corr);
            #pragma unroll
            for (int j = 0; j < 4; ++j) {
                f2_mul(o2[i][j], cd);
                KPs[(2 * (tx + 8 * j))     * 64 + ty + 16 * i] = sv[2 * j];
                KPs[(2 * (tx + 8 * j) + 1) * 64 + ty + 16 * i] = sv[2 * j + 1];
            }
        }
        __syncthreads();

        // O += P V : pairs over dh columns
        #pragma unroll 4
        for (int jj = 0; jj < 64; ++jj) {
            u64 pp[4], vb[4];
            #pragma unroll
            for (int i = 0; i < 4; ++i)
                pp[i] = f2_dup(KPs[jj * 64 + ty + 16 * i]);
            #pragma unroll
            for (int j = 0; j < 4; ++j)
                vb[j] = *reinterpret_cast<const u64*>(&Vs[jj * 64 + 2 * (tx + 8 * j)]);
            #pragma unroll
            for (int i = 0; i < 4; ++i)
                #pragma unroll
                for (int j = 0; j < 4; ++j)
                    f2_fma(o2[i][j], pp[i], vb[j]);
        }
    }

    // normalize + store [b, n, h*64 + c]
    float* aobase = g_ao + ((size_t)(b * SEQ + q0)) * INNER + h * 64;
    #pragma unroll
    for (int i = 0; i < 4; ++i) {
        const float inv = 1.0f / l_run[i];
        #pragma unroll
        for (int j = 0; j < 4; ++j) {
            float2 p = f2_unpack(o2[i][j]);
            p.x *= inv; p.y *= inv;
            *(float2*)(aobase + (size_t)(ty + 16 * i) * INNER + 2 * (tx + 8 * j)) = p;
        }
    }
}

// --------------------------------------------------------------- launcher
extern "C" void kernel_launch(void* const* d_in, const int* in_sizes, int n_in,
                              void* d_out, int out_size) {
    const float* x         = (const float*)d_in[0];
    const float* pose_bias = (const float*)d_in[1];
    const float* ln_gamma  = (const float*)d_in[2];
    const float* ln_beta   = (const float*)d_in[3];
    const float* w_qkv     = (const float*)d_in[4];
    const float* w_out     = (const float*)d_in[5];
    const float* beta      = (const float*)d_in[6];
    float* out = (float*)d_out;

    ln_kernel<<<ROWS, 128>>>(x, ln_gamma, ln_beta);
    sgemm2_kernel<TRIPLE, true><<<dim3(TRIPLE / 128, ROWS / 128), 256>>>(w_qkv, nullptr);
    attn2_kernel<<<dim3(SEQ / 64, BATCH * HEADS), 128>>>(pose_bias, beta);
    sgemm2_kernel<INNER, false><<<dim3(INNER / 128, ROWS / 128), 256>>>(w_out, out);
}

// round 5
// speedup vs baseline: 3.5353x; 3.5353x over previous
#include <cuda_runtime.h>
#include <cuda_bf16.h>
#include <cstdint>
#include <math.h>

#define BATCH  4
#define SEQ    2048
#define DIM    512
#define HEADS  8
#define DHEAD  64
#define INNER  512
#define TRIPLE 1536
#define ROWS   (BATCH * SEQ)

typedef uint32_t u32;
typedef __nv_bfloat16 bf16;

// ----------------------------- device scratch ------------------------------
__device__ bf16 g_xh [ROWS * DIM],   g_xl [ROWS * DIM];     // LN out split
__device__ bf16 g_wqh[TRIPLE * DIM], g_wql[TRIPLE * DIM];   // w_qkv^T split [N][K]
__device__ bf16 g_woh[INNER * DIM],  g_wol[INNER * DIM];    // w_out^T split
__device__ bf16 g_qh [BATCH*HEADS*SEQ*DHEAD], g_ql[BATCH*HEADS*SEQ*DHEAD]; // [b,h,n,dh]
__device__ bf16 g_kh [BATCH*HEADS*SEQ*DHEAD], g_kl[BATCH*HEADS*SEQ*DHEAD]; // [b,h,n,dh]
__device__ bf16 g_vh [BATCH*HEADS*DHEAD*SEQ], g_vl[BATCH*HEADS*DHEAD*SEQ]; // [b,h,dh,n]
__device__ bf16 g_aoh[ROWS * INNER], g_aol[ROWS * INNER];   // attn out split [b,n,h*dh]

// ----------------------------- helpers ---------------------------------
__device__ __forceinline__ u32 smem_u32(const void* p) {
    u32 a;
    asm("{ .reg .u64 t; cvta.to.shared.u64 t, %1; cvt.u32.u64 %0, t; }" : "=r"(a) : "l"(p));
    return a;
}
__device__ __forceinline__ void ldsm4(u32& r0, u32& r1, u32& r2, u32& r3, u32 addr) {
    asm volatile("ldmatrix.sync.aligned.m8n8.x4.shared.b16 {%0,%1,%2,%3}, [%4];"
        : "=r"(r0), "=r"(r1), "=r"(r2), "=r"(r3) : "r"(addr));
}
__device__ __forceinline__ void mma16816(float* c, u32 a0, u32 a1, u32 a2, u32 a3,
                                          u32 b0, u32 b1) {
    asm volatile("mma.sync.aligned.m16n8k16.row.col.f32.bf16.bf16.f32 "
        "{%0,%1,%2,%3}, {%4,%5,%6,%7}, {%8,%9}, {%0,%1,%2,%3};"
        : "+f"(c[0]), "+f"(c[1]), "+f"(c[2]), "+f"(c[3])
        : "r"(a0), "r"(a1), "r"(a2), "r"(a3), "r"(b0), "r"(b1));
}
__device__ __forceinline__ void splitbf(float f, bf16& h, bf16& l) {
    h = __float2bfloat16(f);
    l = __float2bfloat16(f - __bfloat162float(h));
}
__device__ __forceinline__ void split2(float x, float y, u32& hi, u32& lo) {
    __nv_bfloat162 h2 = __floats2bfloat162_rn(x, y);   // low = x, high = y
    float rx = x - __low2float(h2);
    float ry = y - __high2float(h2);
    __nv_bfloat162 l2 = __floats2bfloat162_rn(rx, ry);
    hi = *reinterpret_cast<u32*>(&h2);
    lo = *reinterpret_cast<u32*>(&l2);
}

// ---------------------------------------------------------------- LayerNorm
__global__ __launch_bounds__(128)
void ln_kernel(const float* __restrict__ x,
               const float* __restrict__ gamma,
               const float* __restrict__ beta) {
    const int row = blockIdx.x;
    const int t   = threadIdx.x;
    float4 v = ((const float4*)(x + (size_t)row * DIM))[t];
    float s  = v.x + v.y + v.z + v.w;
    float ss = v.x*v.x + v.y*v.y + v.z*v.z + v.w*v.w;
    #pragma unroll
    for (int o = 16; o > 0; o >>= 1) {
        s  += __shfl_xor_sync(0xffffffffu, s,  o);
        ss += __shfl_xor_sync(0xffffffffu, ss, o);
    }
    __shared__ float sh_s[4], sh_ss[4];
    const int w = t >> 5;
    if ((t & 31) == 0) { sh_s[w] = s; sh_ss[w] = ss; }
    __syncthreads();
    s  = sh_s[0] + sh_s[1] + sh_s[2] + sh_s[3];
    ss = sh_ss[0] + sh_ss[1] + sh_ss[2] + sh_ss[3];
    const float mu  = s * (1.0f / DIM);
    const float var = ss * (1.0f / DIM) - mu * mu;
    const float inv = rsqrtf(var + 1e-5f);
    float4 g  = ((const float4*)gamma)[t];
    float4 be = ((const float4*)beta)[t];
    float o0 = (v.x - mu) * inv * g.x + be.x;
    float o1 = (v.y - mu) * inv * g.y + be.y;
    float o2 = (v.z - mu) * inv * g.z + be.z;
    float o3 = (v.w - mu) * inv * g.w + be.w;
    u32 h01, l01, h23, l23;
    split2(o0, o1, h01, l01);
    split2(o2, o3, h23, l23);
    u32* ph = (u32*)(g_xh + (size_t)row * DIM);
    u32* pl = (u32*)(g_xl + (size_t)row * DIM);
    ph[t * 2] = h01; ph[t * 2 + 1] = h23;
    pl[t * 2] = l01; pl[t * 2 + 1] = l23;
}

// ------------------------------------------- weight transpose + bf16 split
// w [DIM x N] fp32 -> [N x DIM] bf16 hi/lo.  WHICH=0: w_qkv, 1: w_out
template<int WHICH>
__global__ __launch_bounds__(256)
void wprep_kernel(const float* __restrict__ w) {
    const int N = WHICH ? INNER : TRIPLE;
    bf16* th = WHICH ? g_woh : g_wqh;
    bf16* tl = WHICH ? g_wol : g_wql;
    __shared__ float t[32][33];
    const int bx = blockIdx.x * 32;   // n
    const int by = blockIdx.y * 32;   // k
    const int x = threadIdx.x, y = threadIdx.y;
    #pragma unroll
    for (int i = 0; i < 32; i += 8)
        t[y + i][x] = w[(size_t)(by + y + i) * N + bx + x];
    __syncthreads();
    #pragma unroll
    for (int i = 0; i < 32; i += 8) {
        float f = t[x][y + i];
        bf16 h, l; splitbf(f, h, l);
        th[(size_t)(bx + y + i) * DIM + by + x] = h;
        tl[(size_t)(bx + y + i) * DIM + by + x] = l;
    }
}

// ------------------------------------------- HMMA split-bf16 GEMM
// C[8192, NOUT] = A[8192,512] @ W[512,NOUT]; CTA tile 128(m) x 64(n), BK=64.
// 8 warps: warp w owns rows w*16..+15, all 64 n-cols.
// MODE 0: A=g_xh/g_xl, W=g_wqh/g_wql -> scatter into q/k/v split layouts
// MODE 1: A=g_aoh/g_aol, W=g_woh/g_wol -> fp32 C
template<int NOUT, int MODE>
__global__ __launch_bounds__(256)
void hmma_gemm(float* __restrict__ C) {
    __shared__ __align__(128) char sm[49152];   // Ah 0, Al 16K, Bh 32K, Bl 40K
    const u32 sb = smem_u32(sm);
    const int tid = threadIdx.x, w = tid >> 5, lane = tid & 31;
    const int bm = blockIdx.y * 128, bn = blockIdx.x * 64;

    const bf16* Ah = MODE ? g_aoh : g_xh;
    const bf16* Al = MODE ? g_aol : g_xl;
    const bf16* Bh = MODE ? g_woh : g_wqh;
    const bf16* Bl = MODE ? g_wol : g_wql;

    float acc[8][4];
    #pragma unroll
    for (int j = 0; j < 8; ++j)
        #pragma unroll
        for (int i = 0; i < 4; ++i) acc[j][i] = 0.f;

    // ldmatrix lane constants
    const int sw   = (lane & 7) << 4;            // swizzle XOR (row&7)<<4
    const int acb  = lane & 16;                  // A col-byte offset 0/16
    const int bcb  = (lane & 8) << 1;            // B col-byte offset 0/16
    const int rA   = w * 16 + (lane & 15);
    const u32 aoffA = rA * 128;
    const int brow = (lane & 7) + ((lane & 16) >> 1);
    u32 boff[4];
    #pragma unroll
    for (int p = 0; p < 4; ++p) boff[p] = (p * 16 + brow) * 128;

    for (int kt = 0; kt < 8; ++kt) {
        const int k0 = kt * 64;
        // stage A (128x64) hi/lo and B (64x64) hi/lo, SW128-swizzled
        #pragma unroll
        for (int part = 0; part < 2; ++part) {
            const bf16* src = part ? Al : Ah;
            #pragma unroll
            for (int it = 0; it < 4; ++it) {
                int idx = tid + it * 256, r = idx >> 3, ch = idx & 7;
                *(uint4*)(sm + part * 16384 + r * 128 + ((ch * 16) ^ ((r & 7) << 4))) =
                    *(const uint4*)(src + (size_t)(bm + r) * DIM + k0 + ch * 8);
            }
        }
        #pragma unroll
        for (int part = 0; part < 2; ++part) {
            const bf16* src = part ? Bl : Bh;
            #pragma unroll
            for (int it = 0; it < 2; ++it) {
                int idx = tid + it * 256, r = idx >> 3, ch = idx & 7;
                *(uint4*)(sm + 32768 + part * 8192 + r * 128 + ((ch * 16) ^ ((r & 7) << 4))) =
                    *(const uint4*)(src + (size_t)(bn + r) * DIM + k0 + ch * 8);
            }
        }
        __syncthreads();

        #pragma unroll
        for (int pass = 0; pass < 3; ++pass) {
            const u32 ab = sb + (pass == 2 ? 16384 : 0);
            const u32 bb = sb + 32768 + (pass == 1 ? 8192 : 0);
            #pragma unroll
            for (int ks = 0; ks < 4; ++ks) {
                const int kb = ks * 32;
                u32 a0, a1, a2, a3;
                ldsm4(a0, a1, a2, a3, ab + aoffA + (u32)((kb + acb) ^ sw));
                u32 bf[4][4];
                #pragma unroll
                for (int p = 0; p < 4; ++p)
                    ldsm4(bf[p][0], bf[p][1], bf[p][2], bf[p][3],
                          bb + boff[p] + (u32)((kb + bcb) ^ sw));
                #pragma unroll
                for (int ja = 0; ja < 8; ++ja)
                    mma16816(acc[ja], a0, a1, a2, a3,
                             bf[ja >> 1][(ja & 1) * 2], bf[ja >> 1][(ja & 1) * 2 + 1]);
            }
        }
        __syncthreads();
    }

    // ---- epilogue
    const int q  = lane >> 2;
    const int qq = (lane & 3) * 2;
    const int r0 = bm + w * 16 + q;       // second row = r0 + 8
    if (MODE == 1) {
        #pragma unroll
        for (int ja = 0; ja < 8; ++ja) {
            const int col = bn + ja * 8 + qq;
            *(float2*)(C + (size_t)r0 * NOUT + col)       = make_float2(acc[ja][0], acc[ja][1]);
            *(float2*)(C + (size_t)(r0 + 8) * NOUT + col) = make_float2(acc[ja][2], acc[ja][3]);
        }
    } else {
        const int part = bn >> 9;            // 0=q 1=k 2=v
        const int h    = (bn & 511) >> 6;
        const int bb   = r0 >> 11, nn = r0 & 2047;   // r0+8 stays in same b
        const int bh   = bb * HEADS + h;
        if (part == 2) {
            #pragma unroll
            for (int ja = 0; ja < 8; ++ja) {
                #pragma unroll
                for (int e = 0; e < 2; ++e) {
                    const int c = ja * 8 + qq + e;
                    bf16 hh, ll;
                    splitbf(acc[ja][e], hh, ll);
                    g_vh[((size_t)bh * DHEAD + c) * SEQ + nn] = hh;
                    g_vl[((size_t)bh * DHEAD + c) * SEQ + nn] = ll;
                    splitbf(acc[ja][2 + e], hh, ll);
                    g_vh[((size_t)bh * DHEAD + c) * SEQ + nn + 8] = hh;
                    g_vl[((size_t)bh * DHEAD + c) * SEQ + nn + 8] = ll;
                }
            }
        } else {
            bf16* dh = part ? g_kh : g_qh;
            bf16* dl = part ? g_kl : g_ql;
            #pragma unroll
            for (int ja = 0; ja < 8; ++ja) {
                const int col = ja * 8 + qq;
                u32 hi, lo;
                split2(acc[ja][0], acc[ja][1], hi, lo);
                *(u32*)(dh + ((size_t)bh * SEQ + nn) * DHEAD + col) = hi;
                *(u32*)(dl + ((size_t)bh * SEQ + nn) * DHEAD + col) = lo;
                split2(acc[ja][2], acc[ja][3], hi, lo);
                *(u32*)(dh + ((size_t)bh * SEQ + nn + 8) * DHEAD + col) = hi;
                *(u32*)(dl + ((size_t)bh * SEQ + nn + 8) * DHEAD + col) = lo;
            }
        }
    }
}

// ------------------------------------------- HMMA attention
// Block: 256 thr (8 warps), 128 queries of one (b,h); 64-key tiles.
// Warp w owns query rows w*16..+15. Unnormalized softmax (bounded logits);
// P stays in registers (S-accum fragment == PV A-fragment layout).
__global__ __launch_bounds__(256)
void hmma_attn(const float* __restrict__ pose, const float* __restrict__ beta_p) {
    __shared__ __align__(128) char sm[49152];   // Qh 0, Ql 16K, K/V hi 32K, K/V lo 40K
    const u32 sb = smem_u32(sm);
    const int tid = threadIdx.x, w = tid >> 5, lane = tid & 31;
    const int q0 = blockIdx.x * 128, bh = blockIdx.y, b = bh >> 3, h = bh & 7;

    // load Q (128 x 64) hi/lo
    #pragma unroll
    for (int part = 0; part < 2; ++part) {
        const bf16* src = part ? g_ql : g_qh;
        #pragma unroll
        for (int it = 0; it < 4; ++it) {
            int idx = tid + it * 256, r = idx >> 3, ch = idx & 7;
            *(uint4*)(sm + part * 16384 + r * 128 + ((ch * 16) ^ ((r & 7) << 4))) =
                *(const uint4*)(src + ((size_t)bh * SEQ + q0 + r) * DHEAD + ch * 8);
        }
    }

    const float bet = *beta_p;
    const int q  = lane >> 2;
    const int qq = (lane & 3) * 2;
    const float bq0 = bet * __ldg(&pose[(size_t)b * SEQ + q0 + w * 16 + q]);
    const float bq1 = bet * __ldg(&pose[(size_t)b * SEQ + q0 + w * 16 + q + 8]);

    const int sw   = (lane & 7) << 4;
    const int acb  = lane & 16;
    const int bcb  = (lane & 8) << 1;
    const u32 aoff = (w * 16 + (lane & 15)) * 128;
    const int brow = (lane & 7) + ((lane & 16) >> 1);
    u32 boff[4];
    #pragma unroll
    for (int p = 0; p < 4; ++p) boff[p] = (p * 16 + brow) * 128;

    float o[8][4];
    #pragma unroll
    for (int j = 0; j < 8; ++j)
        #pragma unroll
        for (int i = 0; i < 4; ++i) o[j][i] = 0.f;
    float ls0 = 0.f, ls1 = 0.f;

    const bf16* kh = g_kh + (size_t)bh * SEQ * DHEAD;
    const bf16* kl = g_kl + (size_t)bh * SEQ * DHEAD;
    const bf16* vh = g_vh + (size_t)bh * DHEAD * SEQ;
    const bf16* vl = g_vl + (size_t)bh * DHEAD * SEQ;
    const float* pb = pose + (size_t)b * SEQ;

    for (int t = 0; t < 32; ++t) {
        const int j0 = t * 64;
        __syncthreads();   // prev V reads done (also orders Q stores on t=0)
        // stage K tile (64 x 64) hi/lo
        #pragma unroll
        for (int part = 0; part < 2; ++part) {
            const bf16* src = part ? kl : kh;
            #pragma unroll
            for (int it = 0; it < 2; ++it) {
                int idx = tid + it * 256, r = idx >> 3, ch = idx & 7;
                *(uint4*)(sm + 32768 + part * 8192 + r * 128 + ((ch * 16) ^ ((r & 7) << 4))) =
                    *(const uint4*)(src + (size_t)(j0 + r) * DHEAD + ch * 8);
            }
        }
        __syncthreads();

        // S = Q K^T (3 split passes)
        float s[8][4];
        #pragma unroll
        for (int j = 0; j < 8; ++j)
            #pragma unroll
            for (int i = 0; i < 4; ++i) s[j][i] = 0.f;
        #pragma unroll
        for (int pass = 0; pass < 3; ++pass) {
            const u32 ab = sb + (pass == 2 ? 16384 : 0);
            const u32 bb = sb + 32768 + (pass == 1 ? 8192 : 0);
            #pragma unroll
            for (int ks = 0; ks < 4; ++ks) {
                const int kb = ks * 32;
                u32 a0, a1, a2, a3;
                ldsm4(a0, a1, a2, a3, ab + aoff + (u32)((kb + acb) ^ sw));
                u32 bf[4][4];
                #pragma unroll
                for (int p = 0; p < 4; ++p)
                    ldsm4(bf[p][0], bf[p][1], bf[p][2], bf[p][3],
                          bb + boff[p] + (u32)((kb + bcb) ^ sw));
                #pragma unroll
                for (int ja = 0; ja < 8; ++ja)
                    mma16816(s[ja], a0, a1, a2, a3,
                             bf[ja >> 1][(ja & 1) * 2], bf[ja >> 1][(ja & 1) * 2 + 1]);
            }
        }
        __syncthreads();   // all K reads done -> reuse region for V

        // stage V tile (dh 64 x keys 64) hi/lo
        #pragma unroll
        for (int part = 0; part < 2; ++part) {
            const bf16* src = part ? vl : vh;
            #pragma unroll
            for (int it = 0; it < 2; ++it) {
                int idx = tid + it * 256, r = idx >> 3, ch = idx & 7;
                *(uint4*)(sm + 32768 + part * 8192 + r * 128 + ((ch * 16) ^ ((r & 7) << 4))) =
                    *(const uint4*)(src + (size_t)r * SEQ + j0 + ch * 8);
            }
        }

        // softmax (unnormalized) + build P fragments in registers
        u32 Ph[4][4], Pl[4][4];
        #pragma unroll
        for (int ja = 0; ja < 8; ++ja) {
            const int col = ja * 8 + qq;
            const float bk0 = bet * __ldg(&pb[j0 + col]);
            const float bk1 = bet * __ldg(&pb[j0 + col + 1]);
            float e0 = __expf(fmaf(s[ja][0], 0.125f, bq0 + bk0));
            float e1 = __expf(fmaf(s[ja][1], 0.125f, bq0 + bk1));
            float e2 = __expf(fmaf(s[ja][2], 0.125f, bq1 + bk0));
            float e3 = __expf(fmaf(s[ja][3], 0.125f, bq1 + bk1));
            ls0 += e0 + e1;
            ls1 += e2 + e3;
            const int ka = ja >> 1, base = (ja & 1) * 2;
            split2(e0, e1, Ph[ka][base],     Pl[ka][base]);
            split2(e2, e3, Ph[ka][base + 1], Pl[ka][base + 1]);
        }
        __syncthreads();   // V visible

        // O += P V (3 split passes: Ph@Vh, Ph@Vl, Pl@Vh)
        #pragma unroll
        for (int pass = 0; pass < 3; ++pass) {
            const u32 vb = sb + 32768 + (pass == 1 ? 8192 : 0);
            #pragma unroll
            for (int ks = 0; ks < 4; ++ks) {
                u32 bf[4][4];
                #pragma unroll
                for (int p = 0; p < 4; ++p)
                    ldsm4(bf[p][0], bf[p][1], bf[p][2], bf[p][3],
                          vb + boff[p] + (u32)((ks * 32 + bcb) ^ sw));
                const u32* A = (pass == 2) ? Pl[ks] : Ph[ks];
                #pragma unroll
                for (int ja = 0; ja < 8; ++ja)
                    mma16816(o[ja], A[0], A[1], A[2], A[3],
                             bf[ja >> 1][(ja & 1) * 2], bf[ja >> 1][(ja & 1) * 2 + 1]);
            }
        }
    }

    // row sums: cols of one row are spread across the quad (lane^1, lane^2)
    ls0 += __shfl_xor_sync(0xffffffffu, ls0, 1);
    ls0 += __shfl_xor_sync(0xffffffffu, ls0, 2);
    ls1 += __shfl_xor_sync(0xffffffffu, ls1, 1);
    ls1 += __shfl_xor_sync(0xffffffffu, ls1, 2);
    const float inv0 = 1.0f / ls0, inv1 = 1.0f / ls1;

    const int r0 = q0 + w * 16 + q;
    #pragma unroll
    for (int ja = 0; ja < 8; ++ja) {
        const int col = h * DHEAD + ja * 8 + qq;
        u32 hi, lo;
        split2(o[ja][0] * inv0, o[ja][1] * inv0, hi, lo);
        *(u32*)(g_aoh + ((size_t)(b * SEQ + r0)) * INNER + col) = hi;
        *(u32*)(g_aol + ((size_t)(b * SEQ + r0)) * INNER + col) = lo;
        split2(o[ja][2] * inv1, o[ja][3] * inv1, hi, lo);
        *(u32*)(g_aoh + ((size_t)(b * SEQ + r0 + 8)) * INNER + col) = hi;
        *(u32*)(g_aol + ((size_t)(b * SEQ + r0 + 8)) * INNER + col) = lo;
    }
}

// --------------------------------------------------------------- launcher
extern "C" void kernel_launch(void* const* d_in, const int* in_sizes, int n_in,
                              void* d_out, int out_size) {
    const float* x         = (const float*)d_in[0];
    const float* pose_bias = (const float*)d_in[1];
    const float* ln_gamma  = (const float*)d_in[2];
    const float* ln_beta   = (const float*)d_in[3];
    const float* w_qkv     = (const float*)d_in[4];
    const float* w_out     = (const float*)d_in[5];
    const float* beta      = (const float*)d_in[6];
    float* out = (float*)d_out;

    ln_kernel<<<ROWS, 128>>>(x, ln_gamma, ln_beta);
    wprep_kernel<0><<<dim3(TRIPLE / 32, DIM / 32), dim3(32, 8)>>>(w_qkv);
    wprep_kernel<1><<<dim3(INNER / 32, DIM / 32), dim3(32, 8)>>>(w_out);
    hmma_gemm<TRIPLE, 0><<<dim3(TRIPLE / 64, ROWS / 128), 256>>>(nullptr);
    hmma_attn<<<dim3(SEQ / 128, BATCH * HEADS), 256>>>(pose_bias, beta);
    hmma_gemm<INNER, 1><<<dim3(INNER / 64, ROWS / 128), 256>>>(out);
}

// round 6
// speedup vs baseline: 4.2690x; 1.2076x over previous
#include <cuda_runtime.h>
#include <cuda_bf16.h>
#include <cstdint>
#include <math.h>

#define BATCH  4
#define SEQ    2048
#define DIM    512
#define HEADS  8
#define DHEAD  64
#define INNER  512
#define TRIPLE 1536
#define ROWS   (BATCH * SEQ)

typedef uint32_t u32;
typedef __nv_bfloat16 bf16;

// ----------------------------- device scratch ------------------------------
__device__ bf16 g_xh [ROWS * DIM],   g_xl [ROWS * DIM];
__device__ bf16 g_wqh[TRIPLE * DIM], g_wql[TRIPLE * DIM];
__device__ bf16 g_woh[INNER * DIM],  g_wol[INNER * DIM];
__device__ bf16 g_qh [BATCH*HEADS*SEQ*DHEAD], g_ql[BATCH*HEADS*SEQ*DHEAD]; // [b,h,n,dh]
__device__ bf16 g_kh [BATCH*HEADS*SEQ*DHEAD], g_kl[BATCH*HEADS*SEQ*DHEAD]; // [b,h,n,dh]
__device__ bf16 g_vh [BATCH*HEADS*SEQ*DHEAD], g_vl[BATCH*HEADS*SEQ*DHEAD]; // [b,h,n,dh] (row-major now)
__device__ bf16 g_aoh[ROWS * INNER], g_aol[ROWS * INNER];

// ----------------------------- helpers ---------------------------------
__device__ __forceinline__ u32 smem_u32(const void* p) {
    u32 a;
    asm("{ .reg .u64 t; cvta.to.shared.u64 t, %1; cvt.u32.u64 %0, t; }" : "=r"(a) : "l"(p));
    return a;
}
__device__ __forceinline__ void ldsm4(u32& r0, u32& r1, u32& r2, u32& r3, u32 addr) {
    asm volatile("ldmatrix.sync.aligned.m8n8.x4.shared.b16 {%0,%1,%2,%3}, [%4];"
        : "=r"(r0), "=r"(r1), "=r"(r2), "=r"(r3) : "r"(addr));
}
__device__ __forceinline__ void ldsm4t(u32& r0, u32& r1, u32& r2, u32& r3, u32 addr) {
    asm volatile("ldmatrix.sync.aligned.m8n8.x4.trans.shared.b16 {%0,%1,%2,%3}, [%4];"
        : "=r"(r0), "=r"(r1), "=r"(r2), "=r"(r3) : "r"(addr));
}
__device__ __forceinline__ void mma16816(float* c, u32 a0, u32 a1, u32 a2, u32 a3,
                                          u32 b0, u32 b1) {
    asm volatile("mma.sync.aligned.m16n8k16.row.col.f32.bf16.bf16.f32 "
        "{%0,%1,%2,%3}, {%4,%5,%6,%7}, {%8,%9}, {%0,%1,%2,%3};"
        : "+f"(c[0]), "+f"(c[1]), "+f"(c[2]), "+f"(c[3])
        : "r"(a0), "r"(a1), "r"(a2), "r"(a3), "r"(b0), "r"(b1));
}
__device__ __forceinline__ void cpa16(u32 dst, const void* src) {
    asm volatile("cp.async.cg.shared.global [%0], [%1], 16;" :: "r"(dst), "l"(src));
}
#define CP_COMMIT() asm volatile("cp.async.commit_group;" ::: "memory")
#define CP_WAIT(n)  asm volatile("cp.async.wait_group %0;" :: "n"(n) : "memory")

__device__ __forceinline__ void splitbf(float f, bf16& h, bf16& l) {
    h = __float2bfloat16(f);
    l = __float2bfloat16(f - __bfloat162float(h));
}
__device__ __forceinline__ void split2(float x, float y, u32& hi, u32& lo) {
    __nv_bfloat162 h2 = __floats2bfloat162_rn(x, y);
    float rx = x - __low2float(h2);
    float ry = y - __high2float(h2);
    __nv_bfloat162 l2 = __floats2bfloat162_rn(rx, ry);
    hi = *reinterpret_cast<u32*>(&h2);
    lo = *reinterpret_cast<u32*>(&l2);
}

// ---------------------------------------------------------------- LayerNorm
__global__ __launch_bounds__(128)
void ln_kernel(const float* __restrict__ x,
               const float* __restrict__ gamma,
               const float* __restrict__ beta) {
    const int row = blockIdx.x;
    const int t   = threadIdx.x;
    float4 v = ((const float4*)(x + (size_t)row * DIM))[t];
    float s  = v.x + v.y + v.z + v.w;
    float ss = v.x*v.x + v.y*v.y + v.z*v.z + v.w*v.w;
    #pragma unroll
    for (int o = 16; o > 0; o >>= 1) {
        s  += __shfl_xor_sync(0xffffffffu, s,  o);
        ss += __shfl_xor_sync(0xffffffffu, ss, o);
    }
    __shared__ float sh_s[4], sh_ss[4];
    const int w = t >> 5;
    if ((t & 31) == 0) { sh_s[w] = s; sh_ss[w] = ss; }
    __syncthreads();
    s  = sh_s[0] + sh_s[1] + sh_s[2] + sh_s[3];
    ss = sh_ss[0] + sh_ss[1] + sh_ss[2] + sh_ss[3];
    const float mu  = s * (1.0f / DIM);
    const float var = ss * (1.0f / DIM) - mu * mu;
    const float inv = rsqrtf(var + 1e-5f);
    float4 g  = ((const float4*)gamma)[t];
    float4 be = ((const float4*)beta)[t];
    float o0 = (v.x - mu) * inv * g.x + be.x;
    float o1 = (v.y - mu) * inv * g.y + be.y;
    float o2 = (v.z - mu) * inv * g.z + be.z;
    float o3 = (v.w - mu) * inv * g.w + be.w;
    u32 h01, l01, h23, l23;
    split2(o0, o1, h01, l01);
    split2(o2, o3, h23, l23);
    u32* ph = (u32*)(g_xh + (size_t)row * DIM);
    u32* pl = (u32*)(g_xl + (size_t)row * DIM);
    ph[t * 2] = h01; ph[t * 2 + 1] = h23;
    pl[t * 2] = l01; pl[t * 2 + 1] = l23;
}

// ------------------------------------------- weight transpose + bf16 split
template<int WHICH>
__global__ __launch_bounds__(256)
void wprep_kernel(const float* __restrict__ w) {
    const int N = WHICH ? INNER : TRIPLE;
    bf16* th = WHICH ? g_woh : g_wqh;
    bf16* tl = WHICH ? g_wol : g_wql;
    __shared__ float t[32][33];
    const int bx = blockIdx.x * 32;   // n
    const int by = blockIdx.y * 32;   // k
    const int x = threadIdx.x, y = threadIdx.y;
    #pragma unroll
    for (int i = 0; i < 32; i += 8)
        t[y + i][x] = w[(size_t)(by + y + i) * N + bx + x];
    __syncthreads();
    #pragma unroll
    for (int i = 0; i < 32; i += 8) {
        float f = t[x][y + i];
        bf16 h, l; splitbf(f, h, l);
        th[(size_t)(bx + y + i) * DIM + by + x] = h;
        tl[(size_t)(bx + y + i) * DIM + by + x] = l;
    }
}

// ------------------------------------------- HMMA split-bf16 GEMM (cp.async)
// C[8192, NOUT] = A[8192,512] @ W[512,NOUT]; tile 128m x 128n, BK=16, 3 stages.
// Packed layout: 4 rows (32B each) per 128B line, SW128 XOR per line.
// MODE 0: scatter into q/k/v (split, [b,h,n,dh]).  MODE 1: fp32 C.
template<int NOUT, int MODE>
__global__ __launch_bounds__(256)
void hmma_gemm(float* __restrict__ C) {
    __shared__ __align__(128) char sm[49152];   // 3 stages x 16K (Ah,Al,Bh,Bl @ 4K each)
    const u32 sb = smem_u32(sm);
    const int tid = threadIdx.x, w = tid >> 5, lane = tid & 31;
    const int bm = blockIdx.y * 128, bn = blockIdx.x * 128;

    const bf16* Ah = MODE ? g_aoh : g_xh;
    const bf16* Al = MODE ? g_aol : g_xl;
    const bf16* Bh = MODE ? g_woh : g_wqh;
    const bf16* Bl = MODE ? g_wol : g_wql;

    // cp.async mapping: one 16B chunk per matrix per thread
    const int cl = tid >> 3, cs = tid & 7;
    const u32 sdst = cl * 128 + ((cs * 16) ^ ((cl & 7) << 4));
    const int srow = cl * 4 + (cs >> 1);
    const int skel = (cs & 1) * 8;
    const bf16* aH = Ah + (size_t)(bm + srow) * DIM + skel;
    const bf16* aL = Al + (size_t)(bm + srow) * DIM + skel;
    const bf16* bH = Bh + (size_t)(bn + srow) * DIM + skel;
    const bf16* bL = Bl + (size_t)(bn + srow) * DIM + skel;

    // ldmatrix constants (packed 4-rows/line layout)
    const int ar = w * 16 + (lane & 15);
    const int al_ = ar >> 2;
    const u32 aoff = al_ * 128 + ((((ar & 3) * 32) + (lane & 16)) ^ ((al_ & 7) << 4));
    const int brow = (lane & 7) + ((lane & 16) >> 1);
    const int bkb  = (lane & 8) << 1;
    u32 boff[8];
    #pragma unroll
    for (int p = 0; p < 8; ++p) {
        const int r = p * 16 + brow, l = r >> 2;
        boff[p] = l * 128 + ((((r & 3) * 32) + bkb) ^ ((l & 7) << 4));
    }

    float acc[16][4];
    #pragma unroll
    for (int j = 0; j < 16; ++j)
        #pragma unroll
        for (int i = 0; i < 4; ++i) acc[j][i] = 0.f;

    // prologue: stages 0,1
    #pragma unroll
    for (int s = 0; s < 2; ++s) {
        const u32 base = sb + s * 16384;
        const size_t ko = (size_t)s * 16;
        cpa16(base +         sdst, aH + ko);
        cpa16(base +  4096 + sdst, aL + ko);
        cpa16(base +  8192 + sdst, bH + ko);
        cpa16(base + 12288 + sdst, bL + ko);
        CP_COMMIT();
    }

    for (int kt = 0; kt < 32; ++kt) {
        CP_WAIT(1);
        __syncthreads();
        if (kt + 2 < 32) {
            const int s = (kt + 2) % 3;
            const u32 base = sb + s * 16384;
            const size_t ko = (size_t)(kt + 2) * 16;
            cpa16(base +         sdst, aH + ko);
            cpa16(base +  4096 + sdst, aL + ko);
            cpa16(base +  8192 + sdst, bH + ko);
            cpa16(base + 12288 + sdst, bL + ko);
            CP_COMMIT();
        }
        const u32 base = sb + (kt % 3) * 16384;
        #pragma unroll
        for (int pass = 0; pass < 3; ++pass) {
            const u32 ab = base + (pass == 2 ? 4096 : 0);
            const u32 bb = base + 8192 + (pass == 1 ? 4096 : 0);
            u32 a0, a1, a2, a3;
            ldsm4(a0, a1, a2, a3, ab + aoff);
            #pragma unroll
            for (int p = 0; p < 8; ++p) {
                u32 r0, r1, r2, r3;
                ldsm4(r0, r1, r2, r3, bb + boff[p]);
                mma16816(acc[2 * p],     a0, a1, a2, a3, r0, r1);
                mma16816(acc[2 * p + 1], a0, a1, a2, a3, r2, r3);
            }
        }
    }

    // ---- epilogue
    const int q  = lane >> 2;
    const int qq = (lane & 3) * 2;
    const int r0 = bm + w * 16 + q;
    if (MODE == 1) {
        #pragma unroll
        for (int ja = 0; ja < 16; ++ja) {
            const int col = bn + ja * 8 + qq;
            *(float2*)(C + (size_t)r0 * NOUT + col)       = make_float2(acc[ja][0], acc[ja][1]);
            *(float2*)(C + (size_t)(r0 + 8) * NOUT + col) = make_float2(acc[ja][2], acc[ja][3]);
        }
    } else {
        const int part = bn >> 9;            // 0=q 1=k 2=v (128-col block never spans parts)
        bf16* dh = (part == 0) ? g_qh : (part == 1 ? g_kh : g_vh);
        bf16* dl = (part == 0) ? g_ql : (part == 1 ? g_kl : g_vl);
        const int bb = r0 >> 11, nn = r0 & 2047;
        #pragma unroll
        for (int ja = 0; ja < 16; ++ja) {
            const int col = bn + ja * 8 + qq;
            const int h   = (col & 511) >> 6;
            const int d   = col & 63;
            const size_t base = ((size_t)(bb * HEADS + h) * SEQ + nn) * DHEAD + d;
            u32 hi, lo;
            split2(acc[ja][0], acc[ja][1], hi, lo);
            *(u32*)(dh + base) = hi;
            *(u32*)(dl + base) = lo;
            split2(acc[ja][2], acc[ja][3], hi, lo);
            *(u32*)(dh + base + 8 * DHEAD) = hi;
            *(u32*)(dl + base + 8 * DHEAD) = lo;
        }
    }
}

// ------------------------------------------- HMMA attention (cp.async)
// Block: 128 thr (4 warps), 64 queries of one (b,h); 32-key tiles, 2-stage ring.
// Q hi/lo 16K + 2 stages x 16K (Kh,Kl,Vh,Vl @4K). 3 CTAs/SM.
__global__ __launch_bounds__(128, 3)
void hmma_attn(const float* __restrict__ pose, const float* __restrict__ beta_p) {
    __shared__ __align__(128) char sm[49152];
    const u32 sb = smem_u32(sm);
    const int tid = threadIdx.x, w = tid >> 5, lane = tid & 31;
    const int q0 = blockIdx.x * 64, bh = blockIdx.y, b = bh >> 3, h = bh & 7;

    const bf16* kh = g_kh + (size_t)bh * SEQ * DHEAD;
    const bf16* kl = g_kl + (size_t)bh * SEQ * DHEAD;
    const bf16* vh = g_vh + (size_t)bh * SEQ * DHEAD;
    const bf16* vl = g_vl + (size_t)bh * SEQ * DHEAD;

    // Q tiles (hi @0, lo @8K) + first K/V stage, one cp.async group
    {
        const bf16* qh = g_qh + ((size_t)bh * SEQ + q0) * DHEAD;
        const bf16* ql = g_ql + ((size_t)bh * SEQ + q0) * DHEAD;
        #pragma unroll
        for (int i = 0; i < 4; ++i) {
            const int c = tid + i * 128, r = c >> 3, s = c & 7;
            const u32 d = r * 128 + ((s * 16) ^ ((r & 7) << 4));
            const size_t off = (size_t)r * DHEAD + s * 8;
            cpa16(sb + d,        qh + off);
            cpa16(sb + 8192 + d, ql + off);
        }
        #pragma unroll
        for (int i = 0; i < 2; ++i) {
            const int c = tid + i * 128, r = c >> 3, s = c & 7;
            const u32 d = r * 128 + ((s * 16) ^ ((r & 7) << 4));
            const size_t off = (size_t)r * DHEAD + s * 8;
            cpa16(sb + 16384 +         d, kh + off);
            cpa16(sb + 16384 +  4096 + d, kl + off);
            cpa16(sb + 16384 +  8192 + d, vh + off);
            cpa16(sb + 16384 + 12288 + d, vl + off);
        }
        CP_COMMIT();
    }

    const float bet = *beta_p;
    const int q  = lane >> 2;
    const int qq = (lane & 3) * 2;
    const float bq0 = bet * __ldg(&pose[(size_t)b * SEQ + q0 + w * 16 + q]);
    const float bq1 = bet * __ldg(&pose[(size_t)b * SEQ + q0 + w * 16 + q + 8]);
    const float* pb = pose + (size_t)b * SEQ;

    // ldmatrix constants (128B rows everywhere here)
    const u32 swz  = (u32)((lane & 7) << 4);
    const u32 aoff = (u32)((w * 16 + (lane & 15)) * 128);
    const u32 acb  = (u32)(lane & 16);
    const int brow = (lane & 7) + ((lane & 16) >> 1);
    const u32 bcb  = (u32)((lane & 8) << 1);
    const int vrow = (lane & 7) + (lane & 8);
    const u32 vcb  = (u32)(lane & 16);

    float o[8][4];
    #pragma unroll
    for (int j = 0; j < 8; ++j)
        #pragma unroll
        for (int i = 0; i < 4; ++i) o[j][i] = 0.f;
    float ls0 = 0.f, ls1 = 0.f;

    for (int t = 0; t < 64; ++t) {
        const int j0 = t * 32;
        CP_WAIT(0);
        __syncthreads();
        if (t + 1 < 64) {
            const u32 base = sb + 16384 + ((t + 1) & 1) * 16384;
            #pragma unroll
            for (int i = 0; i < 2; ++i) {
                const int c = tid + i * 128, r = c >> 3, s = c & 7;
                const u32 d = r * 128 + ((s * 16) ^ ((r & 7) << 4));
                const size_t off = (size_t)(j0 + 32 + r) * DHEAD + s * 8;
                cpa16(base +         d, kh + off);
                cpa16(base +  4096 + d, kl + off);
                cpa16(base +  8192 + d, vh + off);
                cpa16(base + 12288 + d, vl + off);
            }
            CP_COMMIT();
        }
        const u32 kb_ = sb + 16384 + (t & 1) * 16384;
        const u32 vb_ = kb_ + 8192;

        // ---- S = Q K^T  (m64 per block: warp w rows w*16; n32 keys; k64 dh)
        float s[4][4];
        #pragma unroll
        for (int j = 0; j < 4; ++j)
            #pragma unroll
            for (int i = 0; i < 4; ++i) s[j][i] = 0.f;
        #pragma unroll
        for (int pass = 0; pass < 3; ++pass) {
            const u32 ab = sb + (pass == 2 ? 8192 : 0);
            const u32 bb = kb_ + (pass == 1 ? 4096 : 0);
            #pragma unroll
            for (int ks = 0; ks < 4; ++ks) {
                const u32 kc = (u32)(ks * 32);
                u32 a0, a1, a2, a3;
                ldsm4(a0, a1, a2, a3, ab + aoff + ((kc + acb) ^ swz));
                #pragma unroll
                for (int p = 0; p < 2; ++p) {
                    u32 r0, r1, r2, r3;
                    ldsm4(r0, r1, r2, r3, bb + (u32)((p * 16 + brow) * 128) + ((kc + bcb) ^ swz));
                    mma16816(s[2 * p],     a0, a1, a2, a3, r0, r1);
                    mma16816(s[2 * p + 1], a0, a1, a2, a3, r2, r3);
                }
            }
        }

        // ---- softmax (unnormalized), P fragments in registers
        u32 Ph[2][4], Pl[2][4];
        #pragma unroll
        for (int ja = 0; ja < 4; ++ja) {
            const int col = ja * 8 + qq;
            const float bk0 = bet * __ldg(&pb[j0 + col]);
            const float bk1 = bet * __ldg(&pb[j0 + col + 1]);
            float e0 = __expf(fmaf(s[ja][0], 0.125f, bq0 + bk0));
            float e1 = __expf(fmaf(s[ja][1], 0.125f, bq0 + bk1));
            float e2 = __expf(fmaf(s[ja][2], 0.125f, bq1 + bk0));
            float e3 = __expf(fmaf(s[ja][3], 0.125f, bq1 + bk1));
            ls0 += e0 + e1;
            ls1 += e2 + e3;
            const int ka = ja >> 1, base = (ja & 1) * 2;
            split2(e0, e1, Ph[ka][base],     Pl[ka][base]);
            split2(e2, e3, Ph[ka][base + 1], Pl[ka][base + 1]);
        }

        // ---- O += P V  (n64 dh; k32 keys; V row-major via ldmatrix.trans)
        #pragma unroll
        for (int pass = 0; pass < 3; ++pass) {
            const u32 vb = vb_ + (pass == 1 ? 4096 : 0);
            #pragma unroll
            for (int ks = 0; ks < 2; ++ks) {
                const u32* A = (pass == 2) ? Pl[ks] : Ph[ks];
                const u32 rbase = vb + (u32)((ks * 16 + vrow) * 128);
                #pragma unroll
                for (int p = 0; p < 4; ++p) {
                    u32 r0, r1, r2, r3;
                    ldsm4t(r0, r1, r2, r3, rbase + ((u32)(p * 32 + vcb) ^ swz));
                    mma16816(o[2 * p],     A[0], A[1], A[2], A[3], r0, r1);
                    mma16816(o[2 * p + 1], A[0], A[1], A[2], A[3], r2, r3);
                }
            }
        }
    }

    // row sums live in quads
    ls0 += __shfl_xor_sync(0xffffffffu, ls0, 1);
    ls0 += __shfl_xor_sync(0xffffffffu, ls0, 2);
    ls1 += __shfl_xor_sync(0xffffffffu, ls1, 1);
    ls1 += __shfl_xor_sync(0xffffffffu, ls1, 2);
    const float inv0 = 1.0f / ls0, inv1 = 1.0f / ls1;

    const int r0 = q0 + w * 16 + q;
    #pragma unroll
    for (int ja = 0; ja < 8; ++ja) {
        const int col = h * DHEAD + ja * 8 + qq;
        u32 hi, lo;
        split2(o[ja][0] * inv0, o[ja][1] * inv0, hi, lo);
        *(u32*)(g_aoh + ((size_t)(b * SEQ + r0)) * INNER + col) = hi;
        *(u32*)(g_aol + ((size_t)(b * SEQ + r0)) * INNER + col) = lo;
        split2(o[ja][2] * inv1, o[ja][3] * inv1, hi, lo);
        *(u32*)(g_aoh + ((size_t)(b * SEQ + r0 + 8)) * INNER + col) = hi;
        *(u32*)(g_aol + ((size_t)(b * SEQ + r0 + 8)) * INNER + col) = lo;
    }
}

// --------------------------------------------------------------- launcher
extern "C" void kernel_launch(void* const* d_in, const int* in_sizes, int n_in,
                              void* d_out, int out_size) {
    const float* x         = (const float*)d_in[0];
    const float* pose_bias = (const float*)d_in[1];
    const float* ln_gamma  = (const float*)d_in[2];
    const float* ln_beta   = (const float*)d_in[3];
    const float* w_qkv     = (const float*)d_in[4];
    const float* w_out     = (const float*)d_in[5];
    const float* beta      = (const float*)d_in[6];
    float* out = (float*)d_out;

    ln_kernel<<<ROWS, 128>>>(x, ln_gamma, ln_beta);
    wprep_kernel<0><<<dim3(TRIPLE / 32, DIM / 32), dim3(32, 8)>>>(w_qkv);
    wprep_kernel<1><<<dim3(INNER / 32, DIM / 32), dim3(32, 8)>>>(w_out);
    hmma_gemm<TRIPLE, 0><<<dim3(TRIPLE / 128, ROWS / 128), 256>>>(nullptr);
    hmma_attn<<<dim3(SEQ / 64, BATCH * HEADS), 128>>>(pose_bias, beta);
    hmma_gemm<INNER, 1><<<dim3(INNER / 128, ROWS / 128), 256>>>(out);
}

// round 7
// speedup vs baseline: 4.5763x; 1.0720x over previous
#include <cuda_runtime.h>
#include <cuda_bf16.h>
#include <cstdint>
#include <math.h>

#define BATCH  4
#define SEQ    2048
#define DIM    512
#define HEADS  8
#define DHEAD  64
#define INNER  512
#define TRIPLE 1536
#define ROWS   (BATCH * SEQ)

typedef uint32_t u32;
typedef __nv_bfloat16 bf16;

// ----------------------------- device scratch ------------------------------
__device__ bf16 g_xh [ROWS * DIM],   g_xl [ROWS * DIM];
__device__ bf16 g_wqh[TRIPLE * DIM], g_wql[TRIPLE * DIM];
__device__ bf16 g_woh[INNER * DIM],  g_wol[INNER * DIM];
__device__ bf16 g_qh [BATCH*HEADS*SEQ*DHEAD], g_ql[BATCH*HEADS*SEQ*DHEAD]; // [b,h,n,dh]
__device__ bf16 g_kh [BATCH*HEADS*SEQ*DHEAD], g_kl[BATCH*HEADS*SEQ*DHEAD]; // [b,h,n,dh]
__device__ bf16 g_vh [BATCH*HEADS*SEQ*DHEAD], g_vl[BATCH*HEADS*SEQ*DHEAD]; // [b,h,n,dh]
__device__ bf16 g_aoh[ROWS * INNER], g_aol[ROWS * INNER];

// ----------------------------- helpers ---------------------------------
__device__ __forceinline__ u32 smem_u32(const void* p) {
    u32 a;
    asm("{ .reg .u64 t; cvta.to.shared.u64 t, %1; cvt.u32.u64 %0, t; }" : "=r"(a) : "l"(p));
    return a;
}
__device__ __forceinline__ void ldsm4(u32& r0, u32& r1, u32& r2, u32& r3, u32 addr) {
    asm volatile("ldmatrix.sync.aligned.m8n8.x4.shared.b16 {%0,%1,%2,%3}, [%4];"
        : "=r"(r0), "=r"(r1), "=r"(r2), "=r"(r3) : "r"(addr));
}
__device__ __forceinline__ void ldsm4t(u32& r0, u32& r1, u32& r2, u32& r3, u32 addr) {
    asm volatile("ldmatrix.sync.aligned.m8n8.x4.trans.shared.b16 {%0,%1,%2,%3}, [%4];"
        : "=r"(r0), "=r"(r1), "=r"(r2), "=r"(r3) : "r"(addr));
}
__device__ __forceinline__ void mma16816(float* c, u32 a0, u32 a1, u32 a2, u32 a3,
                                          u32 b0, u32 b1) {
    asm volatile("mma.sync.aligned.m16n8k16.row.col.f32.bf16.bf16.f32 "
        "{%0,%1,%2,%3}, {%4,%5,%6,%7}, {%8,%9}, {%0,%1,%2,%3};"
        : "+f"(c[0]), "+f"(c[1]), "+f"(c[2]), "+f"(c[3])
        : "r"(a0), "r"(a1), "r"(a2), "r"(a3), "r"(b0), "r"(b1));
}
__device__ __forceinline__ void cpa16(u32 dst, const void* src) {
    asm volatile("cp.async.cg.shared.global [%0], [%1], 16;" :: "r"(dst), "l"(src));
}
#define CP_COMMIT() asm volatile("cp.async.commit_group;" ::: "memory")
#define CP_WAIT(n)  asm volatile("cp.async.wait_group %0;" :: "n"(n) : "memory")

__device__ __forceinline__ void splitbf(float f, bf16& h, bf16& l) {
    h = __float2bfloat16(f);
    l = __float2bfloat16(f - __bfloat162float(h));
}
__device__ __forceinline__ void split2(float x, float y, u32& hi, u32& lo) {
    __nv_bfloat162 h2 = __floats2bfloat162_rn(x, y);
    float rx = x - __low2float(h2);
    float ry = y - __high2float(h2);
    __nv_bfloat162 l2 = __floats2bfloat162_rn(rx, ry);
    hi = *reinterpret_cast<u32*>(&h2);
    lo = *reinterpret_cast<u32*>(&l2);
}

// ---------------------------------------------------------------- LayerNorm
__global__ __launch_bounds__(128)
void ln_kernel(const float* __restrict__ x,
               const float* __restrict__ gamma,
               const float* __restrict__ beta) {
    const int row = blockIdx.x;
    const int t   = threadIdx.x;
    float4 v = ((const float4*)(x + (size_t)row * DIM))[t];
    float s  = v.x + v.y + v.z + v.w;
    float ss = v.x*v.x + v.y*v.y + v.z*v.z + v.w*v.w;
    #pragma unroll
    for (int o = 16; o > 0; o >>= 1) {
        s  += __shfl_xor_sync(0xffffffffu, s,  o);
        ss += __shfl_xor_sync(0xffffffffu, ss, o);
    }
    __shared__ float sh_s[4], sh_ss[4];
    const int w = t >> 5;
    if ((t & 31) == 0) { sh_s[w] = s; sh_ss[w] = ss; }
    __syncthreads();
    s  = sh_s[0] + sh_s[1] + sh_s[2] + sh_s[3];
    ss = sh_ss[0] + sh_ss[1] + sh_ss[2] + sh_ss[3];
    const float mu  = s * (1.0f / DIM);
    const float var = ss * (1.0f / DIM) - mu * mu;
    const float inv = rsqrtf(var + 1e-5f);
    float4 g  = ((const float4*)gamma)[t];
    float4 be = ((const float4*)beta)[t];
    float o0 = (v.x - mu) * inv * g.x + be.x;
    float o1 = (v.y - mu) * inv * g.y + be.y;
    float o2 = (v.z - mu) * inv * g.z + be.z;
    float o3 = (v.w - mu) * inv * g.w + be.w;
    u32 h01, l01, h23, l23;
    split2(o0, o1, h01, l01);
    split2(o2, o3, h23, l23);
    u32* ph = (u32*)(g_xh + (size_t)row * DIM);
    u32* pl = (u32*)(g_xl + (size_t)row * DIM);
    ph[t * 2] = h01; ph[t * 2 + 1] = h23;
    pl[t * 2] = l01; pl[t * 2 + 1] = l23;
}

// ------------------------------------------- weight transpose + bf16 split
template<int WHICH>
__global__ __launch_bounds__(256)
void wprep_kernel(const float* __restrict__ w) {
    const int N = WHICH ? INNER : TRIPLE;
    bf16* th = WHICH ? g_woh : g_wqh;
    bf16* tl = WHICH ? g_wol : g_wql;
    __shared__ float t[32][33];
    const int bx = blockIdx.x * 32;   // n
    const int by = blockIdx.y * 32;   // k
    const int x = threadIdx.x, y = threadIdx.y;
    #pragma unroll
    for (int i = 0; i < 32; i += 8)
        t[y + i][x] = w[(size_t)(by + y + i) * N + bx + x];
    __syncthreads();
    #pragma unroll
    for (int i = 0; i < 32; i += 8) {
        float f = t[x][y + i];
        bf16 h, l; splitbf(f, h, l);
        th[(size_t)(bx + y + i) * DIM + by + x] = h;
        tl[(size_t)(bx + y + i) * DIM + by + x] = l;
    }
}

// ------------------------------------------- HMMA split-bf16 GEMM (cp.async)
// C[8192, NOUT] = A[8192,512] @ W[512,NOUT]; tile 128m x 128n, BK=16, 3 stages.
// 512 threads / 16 warps; warp (wm = w>>1, wn = w&1) owns 16m x 64n.
// Packed layout: 4 rows (32B each) per 128B line, SW128 XOR per line.
template<int NOUT, int MODE>
__global__ __launch_bounds__(512)
void hmma_gemm(float* __restrict__ C) {
    __shared__ __align__(128) char sm[49152];   // 3 stages x 16K (Ah,Al,Bh,Bl @ 4K each)
    const u32 sb = smem_u32(sm);
    const int tid = threadIdx.x, w = tid >> 5, lane = tid & 31;
    const int wm = w >> 1, wn = w & 1;
    const int bm = blockIdx.y * 128, bn = blockIdx.x * 128;

    const bf16* Ah = MODE ? g_aoh : g_xh;
    const bf16* Al = MODE ? g_aol : g_xl;
    const bf16* Bh = MODE ? g_woh : g_wqh;
    const bf16* Bl = MODE ? g_wol : g_wql;

    // cp.async mapping: 512 threads, 2 chunks each (one A-split, one B-split)
    const int cc  = tid & 255;                 // chunk within matrix
    const int mat = tid >> 8;                  // 0 = hi, 1 = lo
    const int cl = cc >> 3, cs = cc & 7;
    const u32 sdst = cl * 128 + ((cs * 16) ^ ((cl & 7) << 4));
    const int srow = cl * 4 + (cs >> 1);
    const int skel = (cs & 1) * 8;
    const bf16* aSrc = (mat ? Al : Ah) + (size_t)(bm + srow) * DIM + skel;
    const bf16* bSrc = (mat ? Bl : Bh) + (size_t)(bn + srow) * DIM + skel;
    const u32 aDst = (u32)(mat * 4096) + sdst;
    const u32 bDst = 8192u + (u32)(mat * 4096) + sdst;

    // ldmatrix constants (packed 4-rows/line layout)
    const int ar  = wm * 16 + (lane & 15);
    const int al_ = ar >> 2;
    const u32 aoff = al_ * 128 + ((((ar & 3) * 32) + (lane & 16)) ^ ((al_ & 7) << 4));
    const int brow = (lane & 7) + ((lane & 16) >> 1);
    const int bkb  = (lane & 8) << 1;
    u32 boff[4];
    #pragma unroll
    for (int p = 0; p < 4; ++p) {
        const int r = wn * 64 + p * 16 + brow, l = r >> 2;
        boff[p] = l * 128 + ((((r & 3) * 32) + bkb) ^ ((l & 7) << 4));
    }

    float acc[8][4];
    #pragma unroll
    for (int j = 0; j < 8; ++j)
        #pragma unroll
        for (int i = 0; i < 4; ++i) acc[j][i] = 0.f;

    // prologue: stages 0,1
    #pragma unroll
    for (int s = 0; s < 2; ++s) {
        const u32 base = sb + s * 16384;
        const size_t ko = (size_t)s * 16;
        cpa16(base + aDst, aSrc + ko);
        cpa16(base + bDst, bSrc + ko);
        CP_COMMIT();
    }

    for (int kt = 0; kt < 32; ++kt) {
        CP_WAIT(1);
        __syncthreads();
        if (kt + 2 < 32) {
            const u32 base = sb + ((kt + 2) % 3) * 16384;
            const size_t ko = (size_t)(kt + 2) * 16;
            cpa16(base + aDst, aSrc + ko);
            cpa16(base + bDst, bSrc + ko);
            CP_COMMIT();
        }
        const u32 base = sb + (kt % 3) * 16384;
        #pragma unroll
        for (int pass = 0; pass < 3; ++pass) {
            const u32 ab = base + (pass == 2 ? 4096 : 0);
            const u32 bb = base + 8192 + (pass == 1 ? 4096 : 0);
            u32 a0, a1, a2, a3;
            ldsm4(a0, a1, a2, a3, ab + aoff);
            #pragma unroll
            for (int p = 0; p < 4; ++p) {
                u32 r0, r1, r2, r3;
                ldsm4(r0, r1, r2, r3, bb + boff[p]);
                mma16816(acc[2 * p],     a0, a1, a2, a3, r0, r1);
                mma16816(acc[2 * p + 1], a0, a1, a2, a3, r2, r3);
            }
        }
    }

    // ---- epilogue
    const int q  = lane >> 2;
    const int qq = (lane & 3) * 2;
    const int r0 = bm + wm * 16 + q;
    const int cb = bn + wn * 64;
    if (MODE == 1) {
        #pragma unroll
        for (int ja = 0; ja < 8; ++ja) {
            const int col = cb + ja * 8 + qq;
            *(float2*)(C + (size_t)r0 * NOUT + col)       = make_float2(acc[ja][0], acc[ja][1]);
            *(float2*)(C + (size_t)(r0 + 8) * NOUT + col) = make_float2(acc[ja][2], acc[ja][3]);
        }
    } else {
        const int part = bn >> 9;            // 0=q 1=k 2=v (128-block never spans parts)
        bf16* dh = (part == 0) ? g_qh : (part == 1 ? g_kh : g_vh);
        bf16* dl = (part == 0) ? g_ql : (part == 1 ? g_kl : g_vl);
        const int bb = r0 >> 11, nn = r0 & 2047;
        #pragma unroll
        for (int ja = 0; ja < 8; ++ja) {
            const int col = cb + ja * 8 + qq;
            const int h   = (col & 511) >> 6;
            const int d   = col & 63;
            const size_t base = ((size_t)(bb * HEADS + h) * SEQ + nn) * DHEAD + d;
            u32 hi, lo;
            split2(acc[ja][0], acc[ja][1], hi, lo);
            *(u32*)(dh + base) = hi;
            *(u32*)(dl + base) = lo;
            split2(acc[ja][2], acc[ja][3], hi, lo);
            *(u32*)(dh + base + 8 * DHEAD) = hi;
            *(u32*)(dl + base + 8 * DHEAD) = lo;
        }
    }
}

// ------------------------------------------- HMMA attention (cp.async)
// Block: 128 thr (4 warps), 64 queries of one (b,h); 32-key tiles, 2-stage ring.
__global__ __launch_bounds__(128, 3)
void hmma_attn(const float* __restrict__ pose, const float* __restrict__ beta_p) {
    __shared__ __align__(128) char sm[49152];
    const u32 sb = smem_u32(sm);
    const int tid = threadIdx.x, w = tid >> 5, lane = tid & 31;
    const int q0 = blockIdx.x * 64, bh = blockIdx.y, b = bh >> 3, h = bh & 7;

    const bf16* kh = g_kh + (size_t)bh * SEQ * DHEAD;
    const bf16* kl = g_kl + (size_t)bh * SEQ * DHEAD;
    const bf16* vh = g_vh + (size_t)bh * SEQ * DHEAD;
    const bf16* vl = g_vl + (size_t)bh * SEQ * DHEAD;

    {
        const bf16* qh = g_qh + ((size_t)bh * SEQ + q0) * DHEAD;
        const bf16* ql = g_ql + ((size_t)bh * SEQ + q0) * DHEAD;
        #pragma unroll
        for (int i = 0; i < 4; ++i) {
            const int c = tid + i * 128, r = c >> 3, s = c & 7;
            const u32 d = r * 128 + ((s * 16) ^ ((r & 7) << 4));
            const size_t off = (size_t)r * DHEAD + s * 8;
            cpa16(sb + d,        qh + off);
            cpa16(sb + 8192 + d, ql + off);
        }
        #pragma unroll
        for (int i = 0; i < 2; ++i) {
            const int c = tid + i * 128, r = c >> 3, s = c & 7;
            const u32 d = r * 128 + ((s * 16) ^ ((r & 7) << 4));
            const size_t off = (size_t)r * DHEAD + s * 8;
            cpa16(sb + 16384 +         d, kh + off);
            cpa16(sb + 16384 +  4096 + d, kl + off);
            cpa16(sb + 16384 +  8192 + d, vh + off);
            cpa16(sb + 16384 + 12288 + d, vl + off);
        }
        CP_COMMIT();
    }

    const float bet = *beta_p;
    const int q  = lane >> 2;
    const int qq = (lane & 3) * 2;
    const float bq0 = bet * __ldg(&pose[(size_t)b * SEQ + q0 + w * 16 + q]);
    const float bq1 = bet * __ldg(&pose[(size_t)b * SEQ + q0 + w * 16 + q + 8]);
    const float* pb = pose + (size_t)b * SEQ;

    const u32 swz  = (u32)((lane & 7) << 4);
    const u32 aoff = (u32)((w * 16 + (lane & 15)) * 128);
    const u32 acb  = (u32)(lane & 16);
    const int brow = (lane & 7) + ((lane & 16) >> 1);
    const u32 bcb  = (u32)((lane & 8) << 1);
    const int vrow = (lane & 7) + (lane & 8);
    const u32 vcb  = (u32)(lane & 16);

    float o[8][4];
    #pragma unroll
    for (int j = 0; j < 8; ++j)
        #pragma unroll
        for (int i = 0; i < 4; ++i) o[j][i] = 0.f;
    float ls0 = 0.f, ls1 = 0.f;

    for (int t = 0; t < 64; ++t) {
        const int j0 = t * 32;
        CP_WAIT(0);
        __syncthreads();
        if (t + 1 < 64) {
            const u32 base = sb + 16384 + ((t + 1) & 1) * 16384;
            #pragma unroll
            for (int i = 0; i < 2; ++i) {
                const int c = tid + i * 128, r = c >> 3, s = c & 7;
                const u32 d = r * 128 + ((s * 16) ^ ((r & 7) << 4));
                const size_t off = (size_t)(j0 + 32 + r) * DHEAD + s * 8;
                cpa16(base +         d, kh + off);
                cpa16(base +  4096 + d, kl + off);
                cpa16(base +  8192 + d, vh + off);
                cpa16(base + 12288 + d, vl + off);
            }
            CP_COMMIT();
        }
        const u32 kb_ = sb + 16384 + (t & 1) * 16384;
        const u32 vb_ = kb_ + 8192;

        float s[4][4];
        #pragma unroll
        for (int j = 0; j < 4; ++j)
            #pragma unroll
            for (int i = 0; i < 4; ++i) s[j][i] = 0.f;
        #pragma unroll
        for (int pass = 0; pass < 3; ++pass) {
            const u32 ab = sb + (pass == 2 ? 8192 : 0);
            const u32 bb = kb_ + (pass == 1 ? 4096 : 0);
            #pragma unroll
            for (int ks = 0; ks < 4; ++ks) {
                const u32 kc = (u32)(ks * 32);
                u32 a0, a1, a2, a3;
                ldsm4(a0, a1, a2, a3, ab + aoff + ((kc + acb) ^ swz));
                #pragma unroll
                for (int p = 0; p < 2; ++p) {
                    u32 r0, r1, r2, r3;
                    ldsm4(r0, r1, r2, r3, bb + (u32)((p * 16 + brow) * 128) + ((kc + bcb) ^ swz));
                    mma16816(s[2 * p],     a0, a1, a2, a3, r0, r1);
                    mma16816(s[2 * p + 1], a0, a1, a2, a3, r2, r3);
                }
            }
        }

        u32 Ph[2][4], Pl[2][4];
        #pragma unroll
        for (int ja = 0; ja < 4; ++ja) {
            const int col = ja * 8 + qq;
            const float bk0 = bet * __ldg(&pb[j0 + col]);
            const float bk1 = bet * __ldg(&pb[j0 + col + 1]);
            float e0 = __expf(fmaf(s[ja][0], 0.125f, bq0 + bk0));
            float e1 = __expf(fmaf(s[ja][1], 0.125f, bq0 + bk1));
            float e2 = __expf(fmaf(s[ja][2], 0.125f, bq1 + bk0));
            float e3 = __expf(fmaf(s[ja][3], 0.125f, bq1 + bk1));
            ls0 += e0 + e1;
            ls1 += e2 + e3;
            const int ka = ja >> 1, base = (ja & 1) * 2;
            split2(e0, e1, Ph[ka][base],     Pl[ka][base]);
            split2(e2, e3, Ph[ka][base + 1], Pl[ka][base + 1]);
        }

        #pragma unroll
        for (int pass = 0; pass < 3; ++pass) {
            const u32 vb = vb_ + (pass == 1 ? 4096 : 0);
            #pragma unroll
            for (int ks = 0; ks < 2; ++ks) {
                const u32* A = (pass == 2) ? Pl[ks] : Ph[ks];
                const u32 rbase = vb + (u32)((ks * 16 + vrow) * 128);
                #pragma unroll
                for (int p = 0; p < 4; ++p) {
                    u32 r0, r1, r2, r3;
                    ldsm4t(r0, r1, r2, r3, rbase + ((u32)(p * 32 + vcb) ^ swz));
                    mma16816(o[2 * p],     A[0], A[1], A[2], A[3], r0, r1);
                    mma16816(o[2 * p + 1], A[0], A[1], A[2], A[3], r2, r3);
                }
            }
        }
    }

    ls0 += __shfl_xor_sync(0xffffffffu, ls0, 1);
    ls0 += __shfl_xor_sync(0xffffffffu, ls0, 2);
    ls1 += __shfl_xor_sync(0xffffffffu, ls1, 1);
    ls1 += __shfl_xor_sync(0xffffffffu, ls1, 2);
    const float inv0 = 1.0f / ls0, inv1 = 1.0f / ls1;

    const int r0 = q0 + w * 16 + q;
    #pragma unroll
    for (int ja = 0; ja < 8; ++ja) {
        const int col = h * DHEAD + ja * 8 + qq;
        u32 hi, lo;
        split2(o[ja][0] * inv0, o[ja][1] * inv0, hi, lo);
        *(u32*)(g_aoh + ((size_t)(b * SEQ + r0)) * INNER + col) = hi;
        *(u32*)(g_aol + ((size_t)(b * SEQ + r0)) * INNER + col) = lo;
        split2(o[ja][2] * inv1, o[ja][3] * inv1, hi, lo);
        *(u32*)(g_aoh + ((size_t)(b * SEQ + r0 + 8)) * INNER + col) = hi;
        *(u32*)(g_aol + ((size_t)(b * SEQ + r0 + 8)) * INNER + col) = lo;
    }
}

// --------------------------------------------------------------- launcher
extern "C" void kernel_launch(void* const* d_in, const int* in_sizes, int n_in,
                              void* d_out, int out_size) {
    const float* x         = (const float*)d_in[0];
    const float* pose_bias = (const float*)d_in[1];
    const float* ln_gamma  = (const float*)d_in[2];
    const float* ln_beta   = (const float*)d_in[3];
    const float* w_qkv     = (const float*)d_in[4];
    const float* w_out     = (const float*)d_in[5];
    const float* beta      = (const float*)d_in[6];
    float* out = (float*)d_out;

    ln_kernel<<<ROWS, 128>>>(x, ln_gamma, ln_beta);
    wprep_kernel<0><<<dim3(TRIPLE / 32, DIM / 32), dim3(32, 8)>>>(w_qkv);
    wprep_kernel<1><<<dim3(INNER / 32, DIM / 32), dim3(32, 8)>>>(w_out);
    hmma_gemm<TRIPLE, 0><<<dim3(TRIPLE / 128, ROWS / 128), 512>>>(nullptr);
    hmma_attn<<<dim3(SEQ / 64, BATCH * HEADS), 128>>>(pose_bias, beta);
    hmma_gemm<INNER, 1><<<dim3(INNER / 128, ROWS / 128), 512>>>(out);
}

// round 8
// speedup vs baseline: 4.8683x; 1.0638x over previous
#include <cuda_runtime.h>
#include <cuda_bf16.h>
#include <cstdint>
#include <math.h>

#define BATCH  4
#define SEQ    2048
#define DIM    512
#define HEADS  8
#define DHEAD  64
#define INNER  512
#define TRIPLE 1536
#define ROWS   (BATCH * SEQ)

typedef uint32_t u32;
typedef __nv_bfloat16 bf16;

// ----------------------------- device scratch ------------------------------
__device__ bf16 g_xh [ROWS * DIM],   g_xl [ROWS * DIM];
__device__ bf16 g_wqh[TRIPLE * DIM], g_wql[TRIPLE * DIM];
__device__ bf16 g_woh[INNER * DIM],  g_wol[INNER * DIM];
__device__ bf16 g_qh [BATCH*HEADS*SEQ*DHEAD], g_ql[BATCH*HEADS*SEQ*DHEAD]; // [b,h,n,dh]
__device__ bf16 g_kh [BATCH*HEADS*SEQ*DHEAD], g_kl[BATCH*HEADS*SEQ*DHEAD]; // [b,h,n,dh]
__device__ bf16 g_vh [BATCH*HEADS*SEQ*DHEAD], g_vl[BATCH*HEADS*SEQ*DHEAD]; // [b,h,n,dh]
__device__ bf16 g_aoh[ROWS * INNER], g_aol[ROWS * INNER];

// ----------------------------- helpers ---------------------------------
__device__ __forceinline__ u32 smem_u32(const void* p) {
    u32 a;
    asm("{ .reg .u64 t; cvta.to.shared.u64 t, %1; cvt.u32.u64 %0, t; }" : "=r"(a) : "l"(p));
    return a;
}
__device__ __forceinline__ void ldsm4(u32& r0, u32& r1, u32& r2, u32& r3, u32 addr) {
    asm volatile("ldmatrix.sync.aligned.m8n8.x4.shared.b16 {%0,%1,%2,%3}, [%4];"
        : "=r"(r0), "=r"(r1), "=r"(r2), "=r"(r3) : "r"(addr));
}
__device__ __forceinline__ void ldsm4t(u32& r0, u32& r1, u32& r2, u32& r3, u32 addr) {
    asm volatile("ldmatrix.sync.aligned.m8n8.x4.trans.shared.b16 {%0,%1,%2,%3}, [%4];"
        : "=r"(r0), "=r"(r1), "=r"(r2), "=r"(r3) : "r"(addr));
}
__device__ __forceinline__ void mma16816(float* c, u32 a0, u32 a1, u32 a2, u32 a3,
                                          u32 b0, u32 b1) {
    asm volatile("mma.sync.aligned.m16n8k16.row.col.f32.bf16.bf16.f32 "
        "{%0,%1,%2,%3}, {%4,%5,%6,%7}, {%8,%9}, {%0,%1,%2,%3};"
        : "+f"(c[0]), "+f"(c[1]), "+f"(c[2]), "+f"(c[3])
        : "r"(a0), "r"(a1), "r"(a2), "r"(a3), "r"(b0), "r"(b1));
}
__device__ __forceinline__ void cpa16(u32 dst, const void* src) {
    asm volatile("cp.async.cg.shared.global [%0], [%1], 16;" :: "r"(dst), "l"(src));
}
#define CP_COMMIT() asm volatile("cp.async.commit_group;" ::: "memory")
#define CP_WAIT(n)  asm volatile("cp.async.wait_group %0;" :: "n"(n) : "memory")

__device__ __forceinline__ void splitbf(float f, bf16& h, bf16& l) {
    h = __float2bfloat16(f);
    l = __float2bfloat16(f - __bfloat162float(h));
}
__device__ __forceinline__ void split2(float x, float y, u32& hi, u32& lo) {
    __nv_bfloat162 h2 = __floats2bfloat162_rn(x, y);
    float rx = x - __low2float(h2);
    float ry = y - __high2float(h2);
    __nv_bfloat162 l2 = __floats2bfloat162_rn(rx, ry);
    hi = *reinterpret_cast<u32*>(&h2);
    lo = *reinterpret_cast<u32*>(&l2);
}

// ---------------------------------------------------------------- LayerNorm
__global__ __launch_bounds__(128)
void ln_kernel(const float* __restrict__ x,
               const float* __restrict__ gamma,
               const float* __restrict__ beta) {
    const int row = blockIdx.x;
    const int t   = threadIdx.x;
    float4 v = ((const float4*)(x + (size_t)row * DIM))[t];
    float s  = v.x + v.y + v.z + v.w;
    float ss = v.x*v.x + v.y*v.y + v.z*v.z + v.w*v.w;
    #pragma unroll
    for (int o = 16; o > 0; o >>= 1) {
        s  += __shfl_xor_sync(0xffffffffu, s,  o);
        ss += __shfl_xor_sync(0xffffffffu, ss, o);
    }
    __shared__ float sh_s[4], sh_ss[4];
    const int w = t >> 5;
    if ((t & 31) == 0) { sh_s[w] = s; sh_ss[w] = ss; }
    __syncthreads();
    s  = sh_s[0] + sh_s[1] + sh_s[2] + sh_s[3];
    ss = sh_ss[0] + sh_ss[1] + sh_ss[2] + sh_ss[3];
    const float mu  = s * (1.0f / DIM);
    const float var = ss * (1.0f / DIM) - mu * mu;
    const float inv = rsqrtf(var + 1e-5f);
    float4 g  = ((const float4*)gamma)[t];
    float4 be = ((const float4*)beta)[t];
    float o0 = (v.x - mu) * inv * g.x + be.x;
    float o1 = (v.y - mu) * inv * g.y + be.y;
    float o2 = (v.z - mu) * inv * g.z + be.z;
    float o3 = (v.w - mu) * inv * g.w + be.w;
    u32 h01, l01, h23, l23;
    split2(o0, o1, h01, l01);
    split2(o2, o3, h23, l23);
    u32* ph = (u32*)(g_xh + (size_t)row * DIM);
    u32* pl = (u32*)(g_xl + (size_t)row * DIM);
    ph[t * 2] = h01; ph[t * 2 + 1] = h23;
    pl[t * 2] = l01; pl[t * 2 + 1] = l23;
}

// ------------------------------------------- weight transpose + bf16 split
template<int WHICH>
__global__ __launch_bounds__(256)
void wprep_kernel(const float* __restrict__ w) {
    const int N = WHICH ? INNER : TRIPLE;
    bf16* th = WHICH ? g_woh : g_wqh;
    bf16* tl = WHICH ? g_wol : g_wql;
    __shared__ float t[32][33];
    const int bx = blockIdx.x * 32;   // n
    const int by = blockIdx.y * 32;   // k
    const int x = threadIdx.x, y = threadIdx.y;
    #pragma unroll
    for (int i = 0; i < 32; i += 8)
        t[y + i][x] = w[(size_t)(by + y + i) * N + bx + x];
    __syncthreads();
    #pragma unroll
    for (int i = 0; i < 32; i += 8) {
        float f = t[x][y + i];
        bf16 h, l; splitbf(f, h, l);
        th[(size_t)(bx + y + i) * DIM + by + x] = h;
        tl[(size_t)(bx + y + i) * DIM + by + x] = l;
    }
}

// ------------------------------------------- HMMA split-bf16 GEMM (cp.async)
// C[8192, NOUT] = A[8192,512] @ W[512,NOUT]; tile 128m x 128n, BK=16, 3 stages.
// 256 threads / 8 warps; warp (wm = w>>1, wn = w&1) owns 32m x 64n.
// Per pass: 2 A-ldsm + 4 B-ldsm -> 16 MMAs (ratio 2.67).
// Packed layout: 4 rows (32B each) per 128B line, SW128 XOR per line.
template<int NOUT, int MODE>
__global__ __launch_bounds__(256, 2)
void hmma_gemm(float* __restrict__ C) {
    __shared__ __align__(128) char sm[49152];   // 3 stages x 16K (Ah,Al,Bh,Bl @ 4K each)
    const u32 sb = smem_u32(sm);
    const int tid = threadIdx.x, w = tid >> 5, lane = tid & 31;
    const int wm = w >> 1, wn = w & 1;
    const int bm = blockIdx.y * 128, bn = blockIdx.x * 128;

    const bf16* Ah = MODE ? g_aoh : g_xh;
    const bf16* Al = MODE ? g_aol : g_xl;
    const bf16* Bh = MODE ? g_woh : g_wqh;
    const bf16* Bl = MODE ? g_wol : g_wql;

    // cp.async mapping: one 16B chunk per matrix per thread (256 thr x 4 matrices)
    const int cl = tid >> 3, cs = tid & 7;
    const u32 sdst = cl * 128 + ((cs * 16) ^ ((cl & 7) << 4));
    const int srow = cl * 4 + (cs >> 1);
    const int skel = (cs & 1) * 8;
    const bf16* aH = Ah + (size_t)(bm + srow) * DIM + skel;
    const bf16* aL = Al + (size_t)(bm + srow) * DIM + skel;
    const bf16* bH = Bh + (size_t)(bn + srow) * DIM + skel;
    const bf16* bL = Bl + (size_t)(bn + srow) * DIM + skel;

    // ldmatrix constants (packed 4-rows/line layout)
    const int ar0 = wm * 32 + (lane & 15);
    const int ar1 = ar0 + 16;
    const int al0 = ar0 >> 2, al1 = ar1 >> 2;
    const u32 aoff0 = al0 * 128 + ((((ar0 & 3) * 32) + (lane & 16)) ^ ((al0 & 7) << 4));
    const u32 aoff1 = al1 * 128 + ((((ar1 & 3) * 32) + (lane & 16)) ^ ((al1 & 7) << 4));
    const int brow = (lane & 7) + ((lane & 16) >> 1);
    const int bkb  = (lane & 8) << 1;
    u32 boff[4];
    #pragma unroll
    for (int p = 0; p < 4; ++p) {
        const int r = wn * 64 + p * 16 + brow, l = r >> 2;
        boff[p] = l * 128 + ((((r & 3) * 32) + bkb) ^ ((l & 7) << 4));
    }

    float acc[16][4];
    #pragma unroll
    for (int j = 0; j < 16; ++j)
        #pragma unroll
        for (int i = 0; i < 4; ++i) acc[j][i] = 0.f;

    // prologue: stages 0,1
    #pragma unroll
    for (int s = 0; s < 2; ++s) {
        const u32 base = sb + s * 16384;
        const size_t ko = (size_t)s * 16;
        cpa16(base +         sdst, aH + ko);
        cpa16(base +  4096 + sdst, aL + ko);
        cpa16(base +  8192 + sdst, bH + ko);
        cpa16(base + 12288 + sdst, bL + ko);
        CP_COMMIT();
    }

    for (int kt = 0; kt < 32; ++kt) {
        CP_WAIT(1);
        __syncthreads();
        if (kt + 2 < 32) {
            const u32 base = sb + ((kt + 2) % 3) * 16384;
            const size_t ko = (size_t)(kt + 2) * 16;
            cpa16(base +         sdst, aH + ko);
            cpa16(base +  4096 + sdst, aL + ko);
            cpa16(base +  8192 + sdst, bH + ko);
            cpa16(base + 12288 + sdst, bL + ko);
            CP_COMMIT();
        }
        const u32 base = sb + (kt % 3) * 16384;
        #pragma unroll
        for (int pass = 0; pass < 3; ++pass) {
            const u32 ab = base + (pass == 2 ? 4096 : 0);
            const u32 bb = base + 8192 + (pass == 1 ? 4096 : 0);
            u32 a0, a1, a2, a3, a4, a5, a6, a7;
            ldsm4(a0, a1, a2, a3, ab + aoff0);
            ldsm4(a4, a5, a6, a7, ab + aoff1);
            #pragma unroll
            for (int p = 0; p < 4; ++p) {
                u32 r0, r1, r2, r3;
                ldsm4(r0, r1, r2, r3, bb + boff[p]);
                mma16816(acc[2 * p],         a0, a1, a2, a3, r0, r1);
                mma16816(acc[2 * p + 1],     a0, a1, a2, a3, r2, r3);
                mma16816(acc[8 + 2 * p],     a4, a5, a6, a7, r0, r1);
                mma16816(acc[8 + 2 * p + 1], a4, a5, a6, a7, r2, r3);
            }
        }
    }

    // ---- epilogue: warp covers rows wm*32 + {0..15, 16..31}, cols wn*64..+63
    const int q  = lane >> 2;
    const int qq = (lane & 3) * 2;
    const int cb = bn + wn * 64;
    #pragma unroll
    for (int half = 0; half < 2; ++half) {
        const int r0 = bm + wm * 32 + half * 16 + q;
        float (*af)[4] = &acc[half * 8];
        if (MODE == 1) {
            #pragma unroll
            for (int ja = 0; ja < 8; ++ja) {
                const int col = cb + ja * 8 + qq;
                *(float2*)(C + (size_t)r0 * NOUT + col)       = make_float2(af[ja][0], af[ja][1]);
                *(float2*)(C + (size_t)(r0 + 8) * NOUT + col) = make_float2(af[ja][2], af[ja][3]);
            }
        } else {
            const int part = bn >> 9;            // 0=q 1=k 2=v (128-block never spans parts)
            bf16* dh = (part == 0) ? g_qh : (part == 1 ? g_kh : g_vh);
            bf16* dl = (part == 0) ? g_ql : (part == 1 ? g_kl : g_vl);
            const int bb = r0 >> 11, nn = r0 & 2047;
            #pragma unroll
            for (int ja = 0; ja < 8; ++ja) {
                const int col = cb + ja * 8 + qq;
                const int h   = (col & 511) >> 6;
                const int d   = col & 63;
                const size_t base = ((size_t)(bb * HEADS + h) * SEQ + nn) * DHEAD + d;
                u32 hi, lo;
                split2(af[ja][0], af[ja][1], hi, lo);
                *(u32*)(dh + base) = hi;
                *(u32*)(dl + base) = lo;
                split2(af[ja][2], af[ja][3], hi, lo);
                *(u32*)(dh + base + 8 * DHEAD) = hi;
                *(u32*)(dl + base + 8 * DHEAD) = lo;
            }
        }
    }
}

// ------------------------------------------- HMMA attention (cp.async)
// Block: 128 thr (4 warps), 64 queries of one (b,h); 32-key tiles, 2-stage ring.
__global__ __launch_bounds__(128, 3)
void hmma_attn(const float* __restrict__ pose, const float* __restrict__ beta_p) {
    __shared__ __align__(128) char sm[49152];
    const u32 sb = smem_u32(sm);
    const int tid = threadIdx.x, w = tid >> 5, lane = tid & 31;
    const int q0 = blockIdx.x * 64, bh = blockIdx.y, b = bh >> 3, h = bh & 7;

    const bf16* kh = g_kh + (size_t)bh * SEQ * DHEAD;
    const bf16* kl = g_kl + (size_t)bh * SEQ * DHEAD;
    const bf16* vh = g_vh + (size_t)bh * SEQ * DHEAD;
    const bf16* vl = g_vl + (size_t)bh * SEQ * DHEAD;

    {
        const bf16* qh = g_qh + ((size_t)bh * SEQ + q0) * DHEAD;
        const bf16* ql = g_ql + ((size_t)bh * SEQ + q0) * DHEAD;
        #pragma unroll
        for (int i = 0; i < 4; ++i) {
            const int c = tid + i * 128, r = c >> 3, s = c & 7;
            const u32 d = r * 128 + ((s * 16) ^ ((r & 7) << 4));
            const size_t off = (size_t)r * DHEAD + s * 8;
            cpa16(sb + d,        qh + off);
            cpa16(sb + 8192 + d, ql + off);
        }
        #pragma unroll
        for (int i = 0; i < 2; ++i) {
            const int c = tid + i * 128, r = c >> 3, s = c & 7;
            const u32 d = r * 128 + ((s * 16) ^ ((r & 7) << 4));
            const size_t off = (size_t)r * DHEAD + s * 8;
            cpa16(sb + 16384 +         d, kh + off);
            cpa16(sb + 16384 +  4096 + d, kl + off);
            cpa16(sb + 16384 +  8192 + d, vh + off);
            cpa16(sb + 16384 + 12288 + d, vl + off);
        }
        CP_COMMIT();
    }

    const float bet = *beta_p;
    const int q  = lane >> 2;
    const int qq = (lane & 3) * 2;
    const float bq0 = bet * __ldg(&pose[(size_t)b * SEQ + q0 + w * 16 + q]);
    const float bq1 = bet * __ldg(&pose[(size_t)b * SEQ + q0 + w * 16 + q + 8]);
    const float* pb = pose + (size_t)b * SEQ;

    const u32 swz  = (u32)((lane & 7) << 4);
    const u32 aoff = (u32)((w * 16 + (lane & 15)) * 128);
    const u32 acb  = (u32)(lane & 16);
    const int brow = (lane & 7) + ((lane & 16) >> 1);
    const u32 bcb  = (u32)((lane & 8) << 1);
    const int vrow = (lane & 7) + (lane & 8);
    const u32 vcb  = (u32)(lane & 16);

    float o[8][4];
    #pragma unroll
    for (int j = 0; j < 8; ++j)
        #pragma unroll
        for (int i = 0; i < 4; ++i) o[j][i] = 0.f;
    float ls0 = 0.f, ls1 = 0.f;

    for (int t = 0; t < 64; ++t) {
        const int j0 = t * 32;
        CP_WAIT(0);
        __syncthreads();
        if (t + 1 < 64) {
            const u32 base = sb + 16384 + ((t + 1) & 1) * 16384;
            #pragma unroll
            for (int i = 0; i < 2; ++i) {
                const int c = tid + i * 128, r = c >> 3, s = c & 7;
                const u32 d = r * 128 + ((s * 16) ^ ((r & 7) << 4));
                const size_t off = (size_t)(j0 + 32 + r) * DHEAD + s * 8;
                cpa16(base +         d, kh + off);
                cpa16(base +  4096 + d, kl + off);
                cpa16(base +  8192 + d, vh + off);
                cpa16(base + 12288 + d, vl + off);
            }
            CP_COMMIT();
        }
        const u32 kb_ = sb + 16384 + (t & 1) * 16384;
        const u32 vb_ = kb_ + 8192;

        float s[4][4];
        #pragma unroll
        for (int j = 0; j < 4; ++j)
            #pragma unroll
            for (int i = 0; i < 4; ++i) s[j][i] = 0.f;
        #pragma unroll
        for (int pass = 0; pass < 3; ++pass) {
            const u32 ab = sb + (pass == 2 ? 8192 : 0);
            const u32 bb = kb_ + (pass == 1 ? 4096 : 0);
            #pragma unroll
            for (int ks = 0; ks < 4; ++ks) {
                const u32 kc = (u32)(ks * 32);
                u32 a0, a1, a2, a3;
                ldsm4(a0, a1, a2, a3, ab + aoff + ((kc + acb) ^ swz));
                #pragma unroll
                for (int p = 0; p < 2; ++p) {
                    u32 r0, r1, r2, r3;
                    ldsm4(r0, r1, r2, r3, bb + (u32)((p * 16 + brow) * 128) + ((kc + bcb) ^ swz));
                    mma16816(s[2 * p],     a0, a1, a2, a3, r0, r1);
                    mma16816(s[2 * p + 1], a0, a1, a2, a3, r2, r3);
                }
            }
        }

        u32 Ph[2][4], Pl[2][4];
        #pragma unroll
        for (int ja = 0; ja < 4; ++ja) {
            const int col = ja * 8 + qq;
            const float bk0 = bet * __ldg(&pb[j0 + col]);
            const float bk1 = bet * __ldg(&pb[j0 + col + 1]);
            float e0 = __expf(fmaf(s[ja][0], 0.125f, bq0 + bk0));
            float e1 = __expf(fmaf(s[ja][1], 0.125f, bq0 + bk1));
            float e2 = __expf(fmaf(s[ja][2], 0.125f, bq1 + bk0));
            float e3 = __expf(fmaf(s[ja][3], 0.125f, bq1 + bk1));
            ls0 += e0 + e1;
            ls1 += e2 + e3;
            const int ka = ja >> 1, base = (ja & 1) * 2;
            split2(e0, e1, Ph[ka][base],     Pl[ka][base]);
            split2(e2, e3, Ph[ka][base + 1], Pl[ka][base + 1]);
        }

        #pragma unroll
        for (int pass = 0; pass < 3; ++pass) {
            const u32 vb = vb_ + (pass == 1 ? 4096 : 0);
            #pragma unroll
            for (int ks = 0; ks < 2; ++ks) {
                const u32* A = (pass == 2) ? Pl[ks] : Ph[ks];
                const u32 rbase = vb + (u32)((ks * 16 + vrow) * 128);
                #pragma unroll
                for (int p = 0; p < 4; ++p) {
                    u32 r0, r1, r2, r3;
                    ldsm4t(r0, r1, r2, r3, rbase + ((u32)(p * 32 + vcb) ^ swz));
                    mma16816(o[2 * p],     A[0], A[1], A[2], A[3], r0, r1);
                    mma16816(o[2 * p + 1], A[0], A[1], A[2], A[3], r2, r3);
                }
            }
        }
    }

    ls0 += __shfl_xor_sync(0xffffffffu, ls0, 1);
    ls0 += __shfl_xor_sync(0xffffffffu, ls0, 2);
    ls1 += __shfl_xor_sync(0xffffffffu, ls1, 1);
    ls1 += __shfl_xor_sync(0xffffffffu, ls1, 2);
    const float inv0 = 1.0f / ls0, inv1 = 1.0f / ls1;

    const int r0 = q0 + w * 16 + q;
    #pragma unroll
    for (int ja = 0; ja < 8; ++ja) {
        const int col = h * DHEAD + ja * 8 + qq;
        u32 hi, lo;
        split2(o[ja][0] * inv0, o[ja][1] * inv0, hi, lo);
        *(u32*)(g_aoh + ((size_t)(b * SEQ + r0)) * INNER + col) = hi;
        *(u32*)(g_aol + ((size_t)(b * SEQ + r0)) * INNER + col) = lo;
        split2(o[ja][2] * inv1, o[ja][3] * inv1, hi, lo);
        *(u32*)(g_aoh + ((size_t)(b * SEQ + r0 + 8)) * INNER + col) = hi;
        *(u32*)(g_aol + ((size_t)(b * SEQ + r0 + 8)) * INNER + col) = lo;
    }
}

// --------------------------------------------------------------- launcher
extern "C" void kernel_launch(void* const* d_in, const int* in_sizes, int n_in,
                              void* d_out, int out_size) {
    const float* x         = (const float*)d_in[0];
    const float* pose_bias = (const float*)d_in[1];
    const float* ln_gamma  = (const float*)d_in[2];
    const float* ln_beta   = (const float*)d_in[3];
    const float* w_qkv     = (const float*)d_in[4];
    const float* w_out     = (const float*)d_in[5];
    const float* beta      = (const float*)d_in[6];
    float* out = (float*)d_out;

    ln_kernel<<<ROWS, 128>>>(x, ln_gamma, ln_beta);
    wprep_kernel<0><<<dim3(TRIPLE / 32, DIM / 32), dim3(32, 8)>>>(w_qkv);
    wprep_kernel<1><<<dim3(INNER / 32, DIM / 32), dim3(32, 8)>>>(w_out);
    hmma_gemm<TRIPLE, 0><<<dim3(TRIPLE / 128, ROWS / 128), 256>>>(nullptr);
    hmma_attn<<<dim3(SEQ / 64, BATCH * HEADS), 128>>>(pose_bias, beta);
    hmma_gemm<INNER, 1><<<dim3(INNER / 128, ROWS / 128), 256>>>(out);
}